// round 2
// baseline (speedup 1.0000x reference)
#include <cuda_runtime.h>
#include <math.h>

#define BSZ 2
#define SEQ 2048
#define EMB 2048
#define NH 32
#define HD 64
#define MROWS (BSZ*SEQ)

// Scratch (device globals: allocation-free per harness rules)
__device__ float g_Q[(size_t)MROWS * EMB];
__device__ float g_K[(size_t)MROWS * EMB];
__device__ float g_V[(size_t)MROWS * EMB];
__device__ float g_Ao[(size_t)MROWS * EMB];

// ---- packed f32x2 helpers (FFMA2 path: only reachable via PTX) -------------
typedef unsigned long long u64t;

__device__ __forceinline__ u64t ffma2(u64t a, u64t b, u64t c) {
    u64t d;
    asm("fma.rn.f32x2 %0, %1, %2, %3;" : "=l"(d) : "l"(a), "l"(b), "l"(c));
    return d;
}
__device__ __forceinline__ u64t fmul2(u64t a, u64t b) {
    u64t d;
    asm("mul.rn.f32x2 %0, %1, %2;" : "=l"(d) : "l"(a), "l"(b));
    return d;
}
__device__ __forceinline__ u64t pack2(float lo, float hi) {
    u64t d;
    asm("mov.b64 %0, {%1, %2};" : "=l"(d) : "f"(lo), "f"(hi));
    return d;
}
__device__ __forceinline__ float2 unpack2(u64t v) {
    float2 r;
    asm("mov.b64 {%0, %1}, %2;" : "=f"(r.x), "=f"(r.y) : "l"(v));
    return r;
}

// ---------------------------------------------------------------------------
// SGEMM: C[M,N] = A[M,K] @ B[K,N] + bias[N]
// 128x128 tile, BK=16, 256 threads, 8x8 per thread, FFMA2 inner product.
// ---------------------------------------------------------------------------
__global__ __launch_bounds__(256, 2)
void sgemm_bias(const float* __restrict__ A, const float* __restrict__ B,
                const float* __restrict__ bias, float* __restrict__ C,
                int M, int N, int K)
{
    const int BM = 128, BN = 128, BK = 16;
    __shared__ float As[BK][BM + 4];
    __shared__ float Bs[BK][BN];

    int tid = threadIdx.x;
    int bm = blockIdx.y * BM;
    int bn = blockIdx.x * BN;
    int tx = tid % 16;
    int ty = tid / 16;

    u64t acc2[8][4];
#pragma unroll
    for (int i = 0; i < 8; i++)
#pragma unroll
        for (int j = 0; j < 4; j++) acc2[i][j] = 0ull;

    int arow  = tid / 4;          // 0..63
    int acol4 = (tid % 4) * 4;    // 0,4,8,12
    int brow  = tid / 32;         // 0..7
    int bcol4 = (tid % 32) * 4;   // 0..124

    for (int k0 = 0; k0 < K; k0 += BK) {
#pragma unroll
        for (int r = 0; r < 2; r++) {
            int m = arow + r * 64;
            float4 v = *(const float4*)&A[(size_t)(bm + m) * K + k0 + acol4];
            As[acol4 + 0][m] = v.x;
            As[acol4 + 1][m] = v.y;
            As[acol4 + 2][m] = v.z;
            As[acol4 + 3][m] = v.w;
        }
#pragma unroll
        for (int r = 0; r < 2; r++) {
            int kk = brow + r * 8;
            *(float4*)&Bs[kk][bcol4] =
                *(const float4*)&B[(size_t)(k0 + kk) * N + bn + bcol4];
        }
        __syncthreads();

#pragma unroll
        for (int kk = 0; kk < BK; kk++) {
            float a[8];
            *(float4*)&a[0] = *(float4*)&As[kk][ty * 8];
            *(float4*)&a[4] = *(float4*)&As[kk][ty * 8 + 4];
            u64t b2[4];
            {
                ulonglong2 t0 = *(const ulonglong2*)&Bs[kk][tx * 8];
                ulonglong2 t1 = *(const ulonglong2*)&Bs[kk][tx * 8 + 4];
                b2[0] = t0.x; b2[1] = t0.y; b2[2] = t1.x; b2[3] = t1.y;
            }
#pragma unroll
            for (int i = 0; i < 8; i++) {
                u64t ad = pack2(a[i], a[i]);
#pragma unroll
                for (int j = 0; j < 4; j++)
                    acc2[i][j] = ffma2(ad, b2[j], acc2[i][j]);
            }
        }
        __syncthreads();
    }

#pragma unroll
    for (int i = 0; i < 8; i++) {
        int m = bm + ty * 8 + i;
#pragma unroll
        for (int jj = 0; jj < 2; jj++) {
            int n = bn + tx * 8 + jj * 4;
            float2 p0 = unpack2(acc2[i][jj * 2 + 0]);
            float2 p1 = unpack2(acc2[i][jj * 2 + 1]);
            float4 o;
            o.x = p0.x + bias[n + 0];
            o.y = p0.y + bias[n + 1];
            o.z = p1.x + bias[n + 2];
            o.w = p1.y + bias[n + 3];
            *(float4*)&C[(size_t)m * N + n] = o;
        }
    }
}

// ---------------------------------------------------------------------------
// Flash attention, causal. RoPE is skipped: the reference rotates q and k by
// the SAME per-head orthogonal rotation (angle depends only on head index),
// so q.k is exactly invariant, and v is never rotated.
// CTA = (q-block of 64 rows, head, batch). 256 threads, 4x4 micro-tiles.
// FFMA2 in both QK^T (packed over d) and PV (packed over head-dim cols).
// ---------------------------------------------------------------------------
#define BQ 64
#define BKV 64
#define SLD 68   // smem row pitch (floats), keeps 16B alignment, de-conflicts

__global__ __launch_bounds__(256, 2)
void flash_attn(const float* __restrict__ Q, const float* __restrict__ K,
                const float* __restrict__ V, float* __restrict__ O)
{
    extern __shared__ float sm[];
    float* Qs = sm;                // [64][SLD]
    float* Ks = Qs + BQ * SLD;
    float* Vs = Ks + BKV * SLD;
    float* Ps = Vs + BKV * SLD;

    int qb = blockIdx.x;
    int h  = blockIdx.y;
    int b  = blockIdx.z;
    int tid = threadIdx.x;
    int tx = tid % 16;
    int ty = tid / 16;
    int q0 = qb * BQ;

    // Load Q tile (64x64)
#pragma unroll
    for (int rr = 0; rr < 4; rr++) {
        int r = ty + rr * 16;
        int c = tx * 4;
        *(float4*)&Qs[r * SLD + c] =
            *(const float4*)&Q[((size_t)(b * SEQ + q0 + r)) * EMB + h * HD + c];
    }

    float m_i[4], l_i[4];
    u64t o2[4][2];   // rows ty*4+i, col pairs (tx*4+0..1, tx*4+2..3)
#pragma unroll
    for (int i = 0; i < 4; i++) {
        m_i[i] = -INFINITY;
        l_i[i] = 0.f;
        o2[i][0] = 0ull;
        o2[i][1] = 0ull;
    }
    const float scale = 0.125f;  // 1/sqrt(64)

    int nkb = qb + 1;  // causal: only kv blocks up to the diagonal
    for (int kb = 0; kb < nkb; kb++) {
        __syncthreads();  // previous PV done; also covers initial Q load
#pragma unroll
        for (int rr = 0; rr < 4; rr++) {
            int r = ty + rr * 16;
            int c = tx * 4;
            size_t g = ((size_t)(b * SEQ + kb * BKV + r)) * EMB + h * HD + c;
            *(float4*)&Ks[r * SLD + c] = *(const float4*)&K[g];
            *(float4*)&Vs[r * SLD + c] = *(const float4*)&V[g];
        }
        __syncthreads();

        // S = Q K^T (4x4 per thread), packed over d (pure dot: no dup needed)
        u64t s2[4][4];
#pragma unroll
        for (int i = 0; i < 4; i++)
#pragma unroll
            for (int j = 0; j < 4; j++) s2[i][j] = 0ull;

        for (int d4 = 0; d4 < 16; d4++) {
            ulonglong2 qv[4], kv[4];
#pragma unroll
            for (int i = 0; i < 4; i++)
                qv[i] = *(const ulonglong2*)&Qs[(ty * 4 + i) * SLD + d4 * 4];
#pragma unroll
            for (int j = 0; j < 4; j++)
                kv[j] = *(const ulonglong2*)&Ks[(tx * 4 + j) * SLD + d4 * 4];
#pragma unroll
            for (int i = 0; i < 4; i++)
#pragma unroll
                for (int j = 0; j < 4; j++) {
                    s2[i][j] = ffma2(qv[i].x, kv[j].x, s2[i][j]);
                    s2[i][j] = ffma2(qv[i].y, kv[j].y, s2[i][j]);
                }
        }

        // reduce pairs, scale + causal mask (only diagonal tile needs masking)
        float s[4][4];
        bool diag = (kb == qb);
#pragma unroll
        for (int i = 0; i < 4; i++) {
            int qr = q0 + ty * 4 + i;
#pragma unroll
            for (int j = 0; j < 4; j++) {
                float2 pr = unpack2(s2[i][j]);
                s[i][j] = (pr.x + pr.y) * scale;
                if (diag) {
                    int kc = kb * BKV + tx * 4 + j;
                    if (kc > qr) s[i][j] = -INFINITY;
                }
            }
        }

        // online softmax per row (rows replicated across the 16 tx threads)
#pragma unroll
        for (int i = 0; i < 4; i++) {
            float mx = fmaxf(fmaxf(s[i][0], s[i][1]), fmaxf(s[i][2], s[i][3]));
#pragma unroll
            for (int off = 1; off < 16; off <<= 1)
                mx = fmaxf(mx, __shfl_xor_sync(0xffffffffu, mx, off));
            float m_new = fmaxf(m_i[i], mx);
            float corr = __expf(m_i[i] - m_new);  // 0 on first tile
            m_i[i] = m_new;
            float rs = 0.f;
#pragma unroll
            for (int j = 0; j < 4; j++) {
                float p = __expf(s[i][j] - m_new);
                s[i][j] = p;
                rs += p;
            }
#pragma unroll
            for (int off = 1; off < 16; off <<= 1)
                rs += __shfl_xor_sync(0xffffffffu, rs, off);
            l_i[i] = l_i[i] * corr + rs;
            u64t cd = pack2(corr, corr);
            o2[i][0] = fmul2(o2[i][0], cd);
            o2[i][1] = fmul2(o2[i][1], cd);
        }

        // write P to smem
#pragma unroll
        for (int i = 0; i < 4; i++) {
            float4 pv = make_float4(s[i][0], s[i][1], s[i][2], s[i][3]);
            *(float4*)&Ps[(ty * 4 + i) * SLD + tx * 4] = pv;
        }
        __syncthreads();

        // O += P @ V : rows ty*4+i, col pairs at tx*4
        for (int kk = 0; kk < BKV; kk++) {
            ulonglong2 vv = *(const ulonglong2*)&Vs[kk * SLD + tx * 4];
#pragma unroll
            for (int i = 0; i < 4; i++) {
                float p = Ps[(ty * 4 + i) * SLD + kk];
                u64t pd = pack2(p, p);
                o2[i][0] = ffma2(pd, vv.x, o2[i][0]);
                o2[i][1] = ffma2(pd, vv.y, o2[i][1]);
            }
        }
    }

    // normalize + store (head-interleaved layout -> feeds output GEMM directly)
#pragma unroll
    for (int i = 0; i < 4; i++) {
        float inv = 1.f / l_i[i];
        int qr = q0 + ty * 4 + i;
        float2 a = unpack2(o2[i][0]);
        float2 bv = unpack2(o2[i][1]);
        float4 ov = make_float4(a.x * inv, a.y * inv, bv.x * inv, bv.y * inv);
        *(float4*)&O[((size_t)(b * SEQ + qr)) * EMB + h * HD + tx * 4] = ov;
    }
}

// ---------------------------------------------------------------------------
// Launch
// ---------------------------------------------------------------------------
extern "C" void kernel_launch(void* const* d_in, const int* in_sizes, int n_in,
                              void* d_out, int out_size)
{
    const float* x  = (const float*)d_in[0];
    const float* Wq = (const float*)d_in[1];
    const float* bq = (const float*)d_in[2];
    const float* Wk = (const float*)d_in[3];
    const float* bk = (const float*)d_in[4];
    const float* Wv = (const float*)d_in[5];
    const float* bv = (const float*)d_in[6];
    const float* Wo = (const float*)d_in[7];
    const float* bo = (const float*)d_in[8];
    float* out = (float*)d_out;

    float *Qp, *Kp, *Vp, *Ap;
    cudaGetSymbolAddress((void**)&Qp, g_Q);
    cudaGetSymbolAddress((void**)&Kp, g_K);
    cudaGetSymbolAddress((void**)&Vp, g_V);
    cudaGetSymbolAddress((void**)&Ap, g_Ao);

    int smem_attn = 4 * BQ * SLD * (int)sizeof(float);  // ~69.6 KB
    cudaFuncSetAttribute(flash_attn, cudaFuncAttributeMaxDynamicSharedMemorySize,
                         smem_attn);

    dim3 gthr(256);
    dim3 ggrid(EMB / 128, MROWS / 128);  // (16, 32)

    // QKV projections (biases included; fp32 exact)
    sgemm_bias<<<ggrid, gthr>>>(x, Wq, bq, Qp, MROWS, EMB, EMB);
    sgemm_bias<<<ggrid, gthr>>>(x, Wk, bk, Kp, MROWS, EMB, EMB);
    sgemm_bias<<<ggrid, gthr>>>(x, Wv, bv, Vp, MROWS, EMB, EMB);

    // Causal attention (RoPE mathematically eliminated — see comment above)
    dim3 agrid(SEQ / BQ, NH, BSZ);  // (32, 32, 2)
    flash_attn<<<agrid, gthr, smem_attn>>>(Qp, Kp, Vp, Ap);

    // Output projection
    sgemm_bias<<<ggrid, gthr>>>(Ap, Wo, bo, out, MROWS, EMB, EMB);
}

// round 5
// speedup vs baseline: 1.6706x; 1.6706x over previous
#include <cuda_runtime.h>
#include <cuda_bf16.h>
#include <cstdint>
#include <math.h>

typedef unsigned int u32;
typedef unsigned long long u64;

#define BSZ 2
#define SEQ 2048
#define EMB 2048
#define NH 32
#define HD 64
#define MROWS (BSZ*SEQ)

// ---------------------------------------------------------------------------
// Scratch (device globals: allocation-free per harness rules)
// ---------------------------------------------------------------------------
__device__ float g_Q[(size_t)MROWS * EMB];
__device__ float g_K[(size_t)MROWS * EMB];
__device__ float g_V[(size_t)MROWS * EMB];
__device__ float g_Ao[(size_t)MROWS * EMB];
// bf16 hi/lo split buffers
__device__ __align__(16) __nv_bfloat16 g_ah[(size_t)MROWS * EMB];
__device__ __align__(16) __nv_bfloat16 g_al[(size_t)MROWS * EMB];
__device__ __align__(16) __nv_bfloat16 g_bh[(size_t)EMB * EMB];   // W^T hi
__device__ __align__(16) __nv_bfloat16 g_bl[(size_t)EMB * EMB];   // W^T lo

// ---------------------------------------------------------------------------
// Warp-MMA helpers (baseline PTX: works on plain sm_103 target)
// ---------------------------------------------------------------------------
__device__ __forceinline__ u32 smem_u32(const void* p) {
    u32 a;
    asm("{ .reg .u64 t; cvta.to.shared.u64 t, %1; cvt.u32.u64 %0, t; }"
        : "=r"(a) : "l"(p));
    return a;
}
__device__ __forceinline__ void ldsm_x4(u32& r0, u32& r1, u32& r2, u32& r3,
                                        u32 addr) {
    asm volatile("ldmatrix.sync.aligned.m8n8.x4.shared.b16 {%0,%1,%2,%3}, [%4];"
                 : "=r"(r0), "=r"(r1), "=r"(r2), "=r"(r3) : "r"(addr));
}
__device__ __forceinline__ void mma_bf16(float* d, const u32* a, const u32* b) {
    asm volatile(
        "mma.sync.aligned.m16n8k16.row.col.f32.bf16.bf16.f32 "
        "{%0,%1,%2,%3}, {%4,%5,%6,%7}, {%8,%9}, {%0,%1,%2,%3};"
        : "+f"(d[0]), "+f"(d[1]), "+f"(d[2]), "+f"(d[3])
        : "r"(a[0]), "r"(a[1]), "r"(a[2]), "r"(a[3]), "r"(b[0]), "r"(b[1]));
}
// 64B-row swizzle: XOR chunk bits [5:4] with row bits (bits [8:7] of offset)
#define SWZ64(o) ((o) ^ (((o) >> 3) & 0x30))

// ---------------------------------------------------------------------------
// Conversion kernels: fp32 -> bf16 (hi) + bf16 residual (lo)
// ---------------------------------------------------------------------------
__global__ void conv_rows(const float* __restrict__ X,
                          __nv_bfloat16* __restrict__ H,
                          __nv_bfloat16* __restrict__ L, int n4)
{
    int i = blockIdx.x * blockDim.x + threadIdx.x;
    if (i >= n4) return;
    float4 v = ((const float4*)X)[i];
    __nv_bfloat16 h0 = __float2bfloat16(v.x), h1 = __float2bfloat16(v.y);
    __nv_bfloat16 h2 = __float2bfloat16(v.z), h3 = __float2bfloat16(v.w);
    __nv_bfloat16 l0 = __float2bfloat16(v.x - __bfloat162float(h0));
    __nv_bfloat16 l1 = __float2bfloat16(v.y - __bfloat162float(h1));
    __nv_bfloat16 l2 = __float2bfloat16(v.z - __bfloat162float(h2));
    __nv_bfloat16 l3 = __float2bfloat16(v.w - __bfloat162float(h3));
    __nv_bfloat162 hv0 = __halves2bfloat162(h0, h1);
    __nv_bfloat162 hv1 = __halves2bfloat162(h2, h3);
    __nv_bfloat162 lv0 = __halves2bfloat162(l0, l1);
    __nv_bfloat162 lv1 = __halves2bfloat162(l2, l3);
    uint2 ho, lo;
    ho.x = *(u32*)&hv0; ho.y = *(u32*)&hv1;
    lo.x = *(u32*)&lv0; lo.y = *(u32*)&lv1;
    ((uint2*)H)[i] = ho;
    ((uint2*)L)[i] = lo;
}

// W[K,N] fp32 -> W^T hi/lo bf16 [N,K]
__global__ void conv_T(const float* __restrict__ W,
                       __nv_bfloat16* __restrict__ Th,
                       __nv_bfloat16* __restrict__ Tl)
{
    __shared__ float t[32][33];
    int n0 = blockIdx.x * 32, k0 = blockIdx.y * 32;
    int x = threadIdx.x, y = threadIdx.y;  // 32 x 8
#pragma unroll
    for (int r = 0; r < 32; r += 8)
        t[y + r][x] = W[(size_t)(k0 + y + r) * EMB + n0 + x];
    __syncthreads();
#pragma unroll
    for (int r = 0; r < 32; r += 8) {
        float v = t[x][y + r];
        __nv_bfloat16 h = __float2bfloat16(v);
        size_t o = (size_t)(n0 + y + r) * EMB + k0 + x;
        Th[o] = h;
        Tl[o] = __float2bfloat16(v - __bfloat162float(h));
    }
}

// ---------------------------------------------------------------------------
// Tensor-core GEMM via mma.sync (bf16 hi/lo split, fp32 accumulate):
//   C[M,N] = A @ W + bias,  A as Ah/Al [M,K],  W as Bh/Bl [N,K] (=W^T).
// CTA: 128x128 tile, 8 warps in 2x4 (warp tile 64x32), BK=32.
// D += Ah*Bh + Ah*Bl + Al*Bh  (Al*Bl term negligible: ~2^-16 relative).
// ---------------------------------------------------------------------------
#define BKC 32

__global__ __launch_bounds__(256, 2)
void gemm_mma(const __nv_bfloat16* __restrict__ Ah,
              const __nv_bfloat16* __restrict__ Al,
              const __nv_bfloat16* __restrict__ Bh,
              const __nv_bfloat16* __restrict__ Bl,
              const float* __restrict__ bias,
              float* __restrict__ C, int M, int N, int K)
{
    __shared__ __nv_bfloat16 sAh[128 * BKC], sAl[128 * BKC];
    __shared__ __nv_bfloat16 sBh[128 * BKC], sBl[128 * BKC];

    int tid = threadIdx.x;
    int wid = tid / 32, lid = tid % 32;
    int wm = wid / 4, wn = wid % 4;        // warp grid 2 x 4
    int bm = blockIdx.y * 128, bn = blockIdx.x * 128;

    u32 baseAh = smem_u32(sAh), baseAl = smem_u32(sAl);
    u32 baseBh = smem_u32(sBh), baseBl = smem_u32(sBl);

    float acc[4][4][4];
#pragma unroll
    for (int mt = 0; mt < 4; mt++)
#pragma unroll
        for (int nt = 0; nt < 4; nt++)
#pragma unroll
            for (int e = 0; e < 4; e++) acc[mt][nt][e] = 0.f;

    // per-lane ldmatrix row/chunk decomposition
    int a_r = (lid & 15);             // row within 16-row mtile
    int a_h = (lid >> 4);             // k-half (0/1)
    int b_n = ((lid >> 4) << 3) + (lid & 7);  // row within 16-col ntile pair
    int b_h = ((lid >> 3) & 1);       // k-half

    for (int it = 0; it < K / BKC; it++) {
        int k0 = it * BKC;
        __syncthreads();   // previous compute done before overwriting smem
#pragma unroll
        for (int cc = 0; cc < 2; cc++) {
            int c = tid + cc * 256;          // 512 16B-chunks per array
            int row = c >> 2, ch = c & 3;
            u32 so = SWZ64((u32)(row * 64 + ch * 16));
            size_t ga = (size_t)(bm + row) * K + k0 + ch * 8;
            size_t gb = (size_t)(bn + row) * K + k0 + ch * 8;
            *(uint4*)((char*)sAh + so) = *(const uint4*)(Ah + ga);
            *(uint4*)((char*)sAl + so) = *(const uint4*)(Al + ga);
            *(uint4*)((char*)sBh + so) = *(const uint4*)(Bh + gb);
            *(uint4*)((char*)sBl + so) = *(const uint4*)(Bl + gb);
        }
        __syncthreads();

#pragma unroll
        for (int ks = 0; ks < 2; ks++) {
            u32 af[4][4], bhf[4][2], blf[4][2];
            // A-hi fragments: 4 mtiles
#pragma unroll
            for (int mt = 0; mt < 4; mt++) {
                int r = wm * 64 + mt * 16 + a_r;
                u32 addr = baseAh + SWZ64((u32)(r * 64 + (ks * 2 + a_h) * 16));
                ldsm_x4(af[mt][0], af[mt][1], af[mt][2], af[mt][3], addr);
            }
            // B-hi and B-lo fragments: 2 x4 each (ntile pairs)
#pragma unroll
            for (int np = 0; np < 2; np++) {
                int n = wn * 32 + np * 16 + b_n;
                u32 off = SWZ64((u32)(n * 64 + (ks * 2 + b_h) * 16));
                ldsm_x4(bhf[np * 2][0], bhf[np * 2][1],
                        bhf[np * 2 + 1][0], bhf[np * 2 + 1][1], baseBh + off);
                ldsm_x4(blf[np * 2][0], blf[np * 2][1],
                        blf[np * 2 + 1][0], blf[np * 2 + 1][1], baseBl + off);
            }
            // hh + hl passes
#pragma unroll
            for (int mt = 0; mt < 4; mt++)
#pragma unroll
                for (int nt = 0; nt < 4; nt++)
                    mma_bf16(acc[mt][nt], af[mt], bhf[nt]);
#pragma unroll
            for (int mt = 0; mt < 4; mt++)
#pragma unroll
                for (int nt = 0; nt < 4; nt++)
                    mma_bf16(acc[mt][nt], af[mt], blf[nt]);
            // reload A-lo into af (hi no longer needed), lh pass
#pragma unroll
            for (int mt = 0; mt < 4; mt++) {
                int r = wm * 64 + mt * 16 + a_r;
                u32 addr = baseAl + SWZ64((u32)(r * 64 + (ks * 2 + a_h) * 16));
                ldsm_x4(af[mt][0], af[mt][1], af[mt][2], af[mt][3], addr);
            }
#pragma unroll
            for (int mt = 0; mt < 4; mt++)
#pragma unroll
                for (int nt = 0; nt < 4; nt++)
                    mma_bf16(acc[mt][nt], af[mt], bhf[nt]);
        }
    }

    // Epilogue: acc -> C (+bias). Lane l owns rows (l/4, l/4+8), cols (l%4)*2.
    int rr = lid >> 2, cc2 = (lid & 3) * 2;
#pragma unroll
    for (int mt = 0; mt < 4; mt++) {
        int r0 = bm + wm * 64 + mt * 16 + rr;
#pragma unroll
        for (int nt = 0; nt < 4; nt++) {
            int col = bn + wn * 32 + nt * 8 + cc2;
            float b0 = bias[col], b1 = bias[col + 1];
            float2 v0 = make_float2(acc[mt][nt][0] + b0, acc[mt][nt][1] + b1);
            float2 v1 = make_float2(acc[mt][nt][2] + b0, acc[mt][nt][3] + b1);
            *(float2*)&C[(size_t)r0 * N + col] = v0;
            *(float2*)&C[(size_t)(r0 + 8) * N + col] = v1;
        }
    }
}

// ---------------------------------------------------------------------------
// Flash attention, causal (round-1 FFMA version — best known).
// RoPE mathematically eliminated: reference rotation depends only on head
// index, so q.k is invariant and v is unrotated.
// ---------------------------------------------------------------------------
#define BQ 64
#define BKV 64
#define SLD 68

__global__ __launch_bounds__(256, 1)
void flash_attn(const float* __restrict__ Q, const float* __restrict__ K,
                const float* __restrict__ V, float* __restrict__ O)
{
    extern __shared__ float smf[];
    float* Qs = smf;
    float* Ks = Qs + BQ * SLD;
    float* Vs = Ks + BKV * SLD;
    float* Ps = Vs + BKV * SLD;

    int qb = blockIdx.x;
    int h  = blockIdx.y;
    int b  = blockIdx.z;
    int tid = threadIdx.x;
    int tx = tid % 16;
    int ty = tid / 16;
    int q0 = qb * BQ;

#pragma unroll
    for (int rr = 0; rr < 4; rr++) {
        int r = ty + rr * 16;
        int c = tx * 4;
        *(float4*)&Qs[r * SLD + c] =
            *(const float4*)&Q[((size_t)(b * SEQ + q0 + r)) * EMB + h * HD + c];
    }

    float m_i[4], l_i[4], o[4][4];
#pragma unroll
    for (int i = 0; i < 4; i++) {
        m_i[i] = -INFINITY;
        l_i[i] = 0.f;
#pragma unroll
        for (int j = 0; j < 4; j++) o[i][j] = 0.f;
    }
    const float scale = 0.125f;

    int nkb = qb + 1;
    for (int kb = 0; kb < nkb; kb++) {
        __syncthreads();
#pragma unroll
        for (int rr = 0; rr < 4; rr++) {
            int r = ty + rr * 16;
            int c = tx * 4;
            size_t g = ((size_t)(b * SEQ + kb * BKV + r)) * EMB + h * HD + c;
            *(float4*)&Ks[r * SLD + c] = *(const float4*)&K[g];
            *(float4*)&Vs[r * SLD + c] = *(const float4*)&V[g];
        }
        __syncthreads();

        float s[4][4];
#pragma unroll
        for (int i = 0; i < 4; i++)
#pragma unroll
            for (int j = 0; j < 4; j++) s[i][j] = 0.f;

        for (int d4 = 0; d4 < 16; d4++) {
            float4 qv[4], kv[4];
#pragma unroll
            for (int i = 0; i < 4; i++)
                qv[i] = *(float4*)&Qs[(ty * 4 + i) * SLD + d4 * 4];
#pragma unroll
            for (int j = 0; j < 4; j++)
                kv[j] = *(float4*)&Ks[(tx * 4 + j) * SLD + d4 * 4];
#pragma unroll
            for (int i = 0; i < 4; i++)
#pragma unroll
                for (int j = 0; j < 4; j++)
                    s[i][j] += qv[i].x * kv[j].x + qv[i].y * kv[j].y +
                               qv[i].z * kv[j].z + qv[i].w * kv[j].w;
        }

        bool diag = (kb == qb);
#pragma unroll
        for (int i = 0; i < 4; i++) {
            int qr = q0 + ty * 4 + i;
#pragma unroll
            for (int j = 0; j < 4; j++) {
                s[i][j] *= scale;
                if (diag) {
                    int kc = kb * BKV + tx * 4 + j;
                    if (kc > qr) s[i][j] = -INFINITY;
                }
            }
        }

#pragma unroll
        for (int i = 0; i < 4; i++) {
            float mx = fmaxf(fmaxf(s[i][0], s[i][1]), fmaxf(s[i][2], s[i][3]));
#pragma unroll
            for (int off = 1; off < 16; off <<= 1)
                mx = fmaxf(mx, __shfl_xor_sync(0xffffffffu, mx, off));
            float m_new = fmaxf(m_i[i], mx);
            float corr = __expf(m_i[i] - m_new);
            m_i[i] = m_new;
            float rs = 0.f;
#pragma unroll
            for (int j = 0; j < 4; j++) {
                float p = __expf(s[i][j] - m_new);
                s[i][j] = p;
                rs += p;
            }
#pragma unroll
            for (int off = 1; off < 16; off <<= 1)
                rs += __shfl_xor_sync(0xffffffffu, rs, off);
            l_i[i] = l_i[i] * corr + rs;
#pragma unroll
            for (int j = 0; j < 4; j++) o[i][j] *= corr;
        }

#pragma unroll
        for (int i = 0; i < 4; i++) {
            float4 pv = make_float4(s[i][0], s[i][1], s[i][2], s[i][3]);
            *(float4*)&Ps[(ty * 4 + i) * SLD + tx * 4] = pv;
        }
        __syncthreads();

        for (int kk = 0; kk < BKV; kk++) {
            float4 vv = *(float4*)&Vs[kk * SLD + tx * 4];
#pragma unroll
            for (int i = 0; i < 4; i++) {
                float p = Ps[(ty * 4 + i) * SLD + kk];
                o[i][0] += p * vv.x;
                o[i][1] += p * vv.y;
                o[i][2] += p * vv.z;
                o[i][3] += p * vv.w;
            }
        }
    }

#pragma unroll
    for (int i = 0; i < 4; i++) {
        float inv = 1.f / l_i[i];
        int qr = q0 + ty * 4 + i;
        float4 ov = make_float4(o[i][0] * inv, o[i][1] * inv,
                                o[i][2] * inv, o[i][3] * inv);
        *(float4*)&O[((size_t)(b * SEQ + qr)) * EMB + h * HD + tx * 4] = ov;
    }
}

// ---------------------------------------------------------------------------
// Launch
// ---------------------------------------------------------------------------
extern "C" void kernel_launch(void* const* d_in, const int* in_sizes, int n_in,
                              void* d_out, int out_size)
{
    const float* x  = (const float*)d_in[0];
    const float* Wq = (const float*)d_in[1];
    const float* bq = (const float*)d_in[2];
    const float* Wk = (const float*)d_in[3];
    const float* bk = (const float*)d_in[4];
    const float* Wv = (const float*)d_in[5];
    const float* bv = (const float*)d_in[6];
    const float* Wo = (const float*)d_in[7];
    const float* bo = (const float*)d_in[8];
    float* out = (float*)d_out;

    float *Qp, *Kp, *Vp, *Ap;
    __nv_bfloat16 *ah, *al, *bh, *bl;
    cudaGetSymbolAddress((void**)&Qp, g_Q);
    cudaGetSymbolAddress((void**)&Kp, g_K);
    cudaGetSymbolAddress((void**)&Vp, g_V);
    cudaGetSymbolAddress((void**)&Ap, g_Ao);
    cudaGetSymbolAddress((void**)&ah, g_ah);
    cudaGetSymbolAddress((void**)&al, g_al);
    cudaGetSymbolAddress((void**)&bh, g_bh);
    cudaGetSymbolAddress((void**)&bl, g_bl);

    int smem_attn = 4 * BQ * SLD * (int)sizeof(float);
    cudaFuncSetAttribute(flash_attn, cudaFuncAttributeMaxDynamicSharedMemorySize,
                         smem_attn);

    dim3 ct(32, 8);
    dim3 cg(EMB / 32, EMB / 32);       // transpose-convert grid
    int n4 = MROWS * EMB / 4;
    dim3 ggrid(EMB / 128, MROWS / 128);  // (16, 32)
    dim3 agrid(SEQ / BQ, NH, BSZ);

    // split x once
    conv_rows<<<(n4 + 255) / 256, 256>>>(x, ah, al, n4);

    // Q = x @ Wq + bq
    conv_T<<<cg, ct>>>(Wq, bh, bl);
    gemm_mma<<<ggrid, 256>>>(ah, al, bh, bl, bq, Qp, MROWS, EMB, EMB);
    // K
    conv_T<<<cg, ct>>>(Wk, bh, bl);
    gemm_mma<<<ggrid, 256>>>(ah, al, bh, bl, bk, Kp, MROWS, EMB, EMB);
    // V
    conv_T<<<cg, ct>>>(Wv, bh, bl);
    gemm_mma<<<ggrid, 256>>>(ah, al, bh, bl, bv, Vp, MROWS, EMB, EMB);

    // Attention
    flash_attn<<<agrid, 256, smem_attn>>>(Qp, Kp, Vp, Ap);

    // out = Ao @ Wo + bo
    conv_rows<<<(n4 + 255) / 256, 256>>>(Ap, ah, al, n4);
    conv_T<<<cg, ct>>>(Wo, bh, bl);
    gemm_mma<<<ggrid, 256>>>(ah, al, bh, bl, bo, out, MROWS, EMB, EMB);
}

// round 6
// speedup vs baseline: 2.7996x; 1.6758x over previous
#include <cuda_runtime.h>
#include <cuda_bf16.h>
#include <cstdint>
#include <math.h>

typedef unsigned int u32;
typedef unsigned long long u64;
typedef unsigned short u16;

#define BSZ 2
#define SEQ 2048
#define EMB 2048
#define NH 32
#define HD 64
#define MROWS (BSZ*SEQ)

// ---------------------------------------------------------------------------
// Scratch (device globals: allocation-free per harness rules)
// ---------------------------------------------------------------------------
__device__ __align__(16) __nv_bfloat16 g_ah[(size_t)MROWS * EMB];
__device__ __align__(16) __nv_bfloat16 g_al[(size_t)MROWS * EMB];
__device__ __align__(16) __nv_bfloat16 g_bh[(size_t)EMB * EMB];   // W^T hi
__device__ __align__(16) __nv_bfloat16 g_bl[(size_t)EMB * EMB];   // W^T lo
__device__ __align__(16) __nv_bfloat16 g_qh[(size_t)MROWS * EMB];
__device__ __align__(16) __nv_bfloat16 g_ql[(size_t)MROWS * EMB];
__device__ __align__(16) __nv_bfloat16 g_kh[(size_t)MROWS * EMB];
__device__ __align__(16) __nv_bfloat16 g_kl[(size_t)MROWS * EMB];
__device__ __align__(16) __nv_bfloat16 g_vh[(size_t)MROWS * EMB];
__device__ __align__(16) __nv_bfloat16 g_vl[(size_t)MROWS * EMB];
__device__ __align__(16) __nv_bfloat16 g_vth[(size_t)MROWS * EMB]; // V^T per (b,h)
__device__ __align__(16) __nv_bfloat16 g_vtl[(size_t)MROWS * EMB];

// ---------------------------------------------------------------------------
// Warp-MMA helpers (baseline PTX: works on plain sm_103 target)
// ---------------------------------------------------------------------------
__device__ __forceinline__ u32 smem_u32(const void* p) {
    u32 a;
    asm("{ .reg .u64 t; cvta.to.shared.u64 t, %1; cvt.u32.u64 %0, t; }"
        : "=r"(a) : "l"(p));
    return a;
}
__device__ __forceinline__ void ldsm_x4(u32& r0, u32& r1, u32& r2, u32& r3,
                                        u32 addr) {
    asm volatile("ldmatrix.sync.aligned.m8n8.x4.shared.b16 {%0,%1,%2,%3}, [%4];"
                 : "=r"(r0), "=r"(r1), "=r"(r2), "=r"(r3) : "r"(addr));
}
__device__ __forceinline__ void mma_bf16(float* d, const u32* a, const u32* b) {
    asm volatile(
        "mma.sync.aligned.m16n8k16.row.col.f32.bf16.bf16.f32 "
        "{%0,%1,%2,%3}, {%4,%5,%6,%7}, {%8,%9}, {%0,%1,%2,%3};"
        : "+f"(d[0]), "+f"(d[1]), "+f"(d[2]), "+f"(d[3])
        : "r"(a[0]), "r"(a[1]), "r"(a[2]), "r"(a[3]), "r"(b[0]), "r"(b[1]));
}
// pack two fp32 -> bf16x2 (lo = x0), plus bf16x2 of the residuals
__device__ __forceinline__ void pack_hl(float x0, float x1, u32& hi, u32& lo) {
    asm("cvt.rn.bf16x2.f32 %0, %1, %2;" : "=r"(hi) : "f"(x1), "f"(x0));
    float h0 = __uint_as_float(hi << 16);
    float h1 = __uint_as_float(hi & 0xFFFF0000u);
    float r0 = x0 - h0, r1 = x1 - h1;
    asm("cvt.rn.bf16x2.f32 %0, %1, %2;" : "=r"(lo) : "f"(r1), "f"(r0));
}
// 64B-row swizzle (GEMM, BK=32 bf16 rows)
#define SWZ64(o) ((o) ^ (((o) >> 3) & 0x30))
// 128B-row swizzle (attention, 64 bf16 rows)
#define SWZ128(o) ((o) ^ (((o) >> 3) & 0x70))

// ---------------------------------------------------------------------------
// Conversion kernels
// ---------------------------------------------------------------------------
__global__ void conv_rows(const float* __restrict__ X,
                          __nv_bfloat16* __restrict__ H,
                          __nv_bfloat16* __restrict__ L, int n4)
{
    int i = blockIdx.x * blockDim.x + threadIdx.x;
    if (i >= n4) return;
    float4 v = ((const float4*)X)[i];
    u32 h0, l0, h1, l1;
    pack_hl(v.x, v.y, h0, l0);
    pack_hl(v.z, v.w, h1, l1);
    ((uint2*)H)[i] = make_uint2(h0, h1);
    ((uint2*)L)[i] = make_uint2(l0, l1);
}

// W[K,N] fp32 -> W^T hi/lo bf16 [N,K]
__global__ void conv_T(const float* __restrict__ W,
                       __nv_bfloat16* __restrict__ Th,
                       __nv_bfloat16* __restrict__ Tl)
{
    __shared__ float t[32][33];
    int n0 = blockIdx.x * 32, k0 = blockIdx.y * 32;
    int x = threadIdx.x, y = threadIdx.y;  // 32 x 8
#pragma unroll
    for (int r = 0; r < 32; r += 8)
        t[y + r][x] = W[(size_t)(k0 + y + r) * EMB + n0 + x];
    __syncthreads();
#pragma unroll
    for (int r = 0; r < 32; r += 8) {
        float v = t[x][y + r];
        __nv_bfloat16 h = __float2bfloat16(v);
        size_t o = (size_t)(n0 + y + r) * EMB + k0 + x;
        Th[o] = h;
        Tl[o] = __float2bfloat16(v - __bfloat162float(h));
    }
}

// Vh/Vl [token][h*64+d] -> VTh/VTl [(b*NH+h)*64+d][seq]
__global__ void conv_vt(const __nv_bfloat16* __restrict__ Vh,
                        const __nv_bfloat16* __restrict__ Vl,
                        __nv_bfloat16* __restrict__ VTh,
                        __nv_bfloat16* __restrict__ VTl)
{
    __shared__ u16 th[32][33], tl[32][33];
    int s0 = blockIdx.x * 32;
    int d0 = (blockIdx.y & 1) * 32;
    int hh = (blockIdx.y >> 1) & 31;
    int b  = blockIdx.y >> 6;
    int x = threadIdx.x, y = threadIdx.y;  // 32 x 8
#pragma unroll
    for (int r = 0; r < 32; r += 8) {
        size_t g = (size_t)(b * SEQ + s0 + y + r) * EMB + hh * HD + d0 + x;
        th[y + r][x] = *(const u16*)(Vh + g);
        tl[y + r][x] = *(const u16*)(Vl + g);
    }
    __syncthreads();
#pragma unroll
    for (int r = 0; r < 32; r += 8) {
        size_t o = ((size_t)((b * NH + hh) * HD) + d0 + y + r) * SEQ + s0 + x;
        *(u16*)(VTh + o) = th[x][y + r];
        *(u16*)(VTl + o) = tl[x][y + r];
    }
}

// ---------------------------------------------------------------------------
// Tensor-core GEMM via mma.sync (bf16 hi/lo split, fp32 accumulate):
//   out = A @ W + bias,  A as Ah/Al [M,K],  W as Bh/Bl [N,K] (=W^T).
// If C != null: write fp32 C. Else: write bf16 hi/lo to H/L.
// ---------------------------------------------------------------------------
#define BKC 32

__global__ __launch_bounds__(256, 2)
void gemm_mma(const __nv_bfloat16* __restrict__ Ah,
              const __nv_bfloat16* __restrict__ Al,
              const __nv_bfloat16* __restrict__ Bh,
              const __nv_bfloat16* __restrict__ Bl,
              const float* __restrict__ bias,
              float* __restrict__ C,
              __nv_bfloat16* __restrict__ H,
              __nv_bfloat16* __restrict__ L,
              int M, int N, int K)
{
    __shared__ __nv_bfloat16 sAh[128 * BKC], sAl[128 * BKC];
    __shared__ __nv_bfloat16 sBh[128 * BKC], sBl[128 * BKC];

    int tid = threadIdx.x;
    int wid = tid / 32, lid = tid % 32;
    int wm = wid / 4, wn = wid % 4;        // warp grid 2 x 4
    int bm = blockIdx.y * 128, bn = blockIdx.x * 128;

    u32 baseAh = smem_u32(sAh), baseAl = smem_u32(sAl);
    u32 baseBh = smem_u32(sBh), baseBl = smem_u32(sBl);

    float acc[4][4][4];
#pragma unroll
    for (int mt = 0; mt < 4; mt++)
#pragma unroll
        for (int nt = 0; nt < 4; nt++)
#pragma unroll
            for (int e = 0; e < 4; e++) acc[mt][nt][e] = 0.f;

    int a_r = (lid & 15);
    int a_h = (lid >> 4);
    int b_n = ((lid >> 4) << 3) + (lid & 7);
    int b_h = ((lid >> 3) & 1);

    for (int it = 0; it < K / BKC; it++) {
        int k0 = it * BKC;
        __syncthreads();
#pragma unroll
        for (int cc = 0; cc < 2; cc++) {
            int c = tid + cc * 256;
            int row = c >> 2, ch = c & 3;
            u32 so = SWZ64((u32)(row * 64 + ch * 16));
            size_t ga = (size_t)(bm + row) * K + k0 + ch * 8;
            size_t gb = (size_t)(bn + row) * K + k0 + ch * 8;
            *(uint4*)((char*)sAh + so) = *(const uint4*)(Ah + ga);
            *(uint4*)((char*)sAl + so) = *(const uint4*)(Al + ga);
            *(uint4*)((char*)sBh + so) = *(const uint4*)(Bh + gb);
            *(uint4*)((char*)sBl + so) = *(const uint4*)(Bl + gb);
        }
        __syncthreads();

#pragma unroll
        for (int ks = 0; ks < 2; ks++) {
            u32 af[4][4], bhf[4][2], blf[4][2];
#pragma unroll
            for (int mt = 0; mt < 4; mt++) {
                int r = wm * 64 + mt * 16 + a_r;
                u32 addr = baseAh + SWZ64((u32)(r * 64 + (ks * 2 + a_h) * 16));
                ldsm_x4(af[mt][0], af[mt][1], af[mt][2], af[mt][3], addr);
            }
#pragma unroll
            for (int np = 0; np < 2; np++) {
                int n = wn * 32 + np * 16 + b_n;
                u32 off = SWZ64((u32)(n * 64 + (ks * 2 + b_h) * 16));
                ldsm_x4(bhf[np * 2][0], bhf[np * 2][1],
                        bhf[np * 2 + 1][0], bhf[np * 2 + 1][1], baseBh + off);
                ldsm_x4(blf[np * 2][0], blf[np * 2][1],
                        blf[np * 2 + 1][0], blf[np * 2 + 1][1], baseBl + off);
            }
#pragma unroll
            for (int mt = 0; mt < 4; mt++)
#pragma unroll
                for (int nt = 0; nt < 4; nt++)
                    mma_bf16(acc[mt][nt], af[mt], bhf[nt]);
#pragma unroll
            for (int mt = 0; mt < 4; mt++)
#pragma unroll
                for (int nt = 0; nt < 4; nt++)
                    mma_bf16(acc[mt][nt], af[mt], blf[nt]);
#pragma unroll
            for (int mt = 0; mt < 4; mt++) {
                int r = wm * 64 + mt * 16 + a_r;
                u32 addr = baseAl + SWZ64((u32)(r * 64 + (ks * 2 + a_h) * 16));
                ldsm_x4(af[mt][0], af[mt][1], af[mt][2], af[mt][3], addr);
            }
#pragma unroll
            for (int mt = 0; mt < 4; mt++)
#pragma unroll
                for (int nt = 0; nt < 4; nt++)
                    mma_bf16(acc[mt][nt], af[mt], bhf[nt]);
        }
    }

    int rr = lid >> 2, cc2 = (lid & 3) * 2;
#pragma unroll
    for (int mt = 0; mt < 4; mt++) {
        int r0 = bm + wm * 64 + mt * 16 + rr;
#pragma unroll
        for (int nt = 0; nt < 4; nt++) {
            int col = bn + wn * 32 + nt * 8 + cc2;
            float b0 = bias[col], b1 = bias[col + 1];
            float v00 = acc[mt][nt][0] + b0, v01 = acc[mt][nt][1] + b1;
            float v10 = acc[mt][nt][2] + b0, v11 = acc[mt][nt][3] + b1;
            if (C) {
                *(float2*)&C[(size_t)r0 * N + col] = make_float2(v00, v01);
                *(float2*)&C[(size_t)(r0 + 8) * N + col] = make_float2(v10, v11);
            } else {
                u32 hi, lo;
                pack_hl(v00, v01, hi, lo);
                *(u32*)&H[(size_t)r0 * N + col] = hi;
                *(u32*)&L[(size_t)r0 * N + col] = lo;
                pack_hl(v10, v11, hi, lo);
                *(u32*)&H[(size_t)(r0 + 8) * N + col] = hi;
                *(u32*)&L[(size_t)(r0 + 8) * N + col] = lo;
            }
        }
    }
}

// ---------------------------------------------------------------------------
// Tensor-core causal flash attention (bf16 hi/lo everywhere, fp32 softmax).
// RoPE mathematically eliminated: the reference rotation depends only on the
// head index, so q.k is invariant and v is unrotated.
// CTA: 128 q rows, 8 warps (warp = 16 q rows x full 64-col kv tile).
// ---------------------------------------------------------------------------
#define ABQ 128
#define ABK 64
#define OQH 0
#define OQL 16384
#define OKH 32768
#define OKL 40960
#define OVH 49152
#define OVL 57344
#define ASMEM 65536

__global__ __launch_bounds__(256)
void flash_attn_tc(const __nv_bfloat16* __restrict__ qh_,
                   const __nv_bfloat16* __restrict__ ql_,
                   const __nv_bfloat16* __restrict__ kh_,
                   const __nv_bfloat16* __restrict__ kl_,
                   const __nv_bfloat16* __restrict__ vth_,
                   const __nv_bfloat16* __restrict__ vtl_,
                   __nv_bfloat16* __restrict__ aoh,
                   __nv_bfloat16* __restrict__ aol)
{
    extern __shared__ char smc[];
    u32 sb = smem_u32(smc);
    int tid = threadIdx.x, wid = tid / 32, lid = tid % 32;
    int qb = blockIdx.x, h = blockIdx.y, b = blockIdx.z;
    int q0 = qb * ABQ;
    int warp_row = q0 + wid * 16;

    // Load Q tile (128x64 hi/lo), SW128 rows
#pragma unroll
    for (int i = 0; i < 4; i++) {
        int c = tid + i * 256;
        int r = c >> 3, ch = c & 7;
        u32 so = SWZ128((u32)(r * 128 + ch * 16));
        size_t g = (size_t)(b * SEQ + q0 + r) * EMB + h * HD + ch * 8;
        *(uint4*)(smc + OQH + so) = *(const uint4*)(qh_ + g);
        *(uint4*)(smc + OQL + so) = *(const uint4*)(ql_ + g);
    }

    float m_i[2], l_i[2], o[8][4];
    m_i[0] = m_i[1] = -INFINITY;
    l_i[0] = l_i[1] = 0.f;
#pragma unroll
    for (int nt = 0; nt < 8; nt++)
#pragma unroll
        for (int e = 0; e < 4; e++) o[nt][e] = 0.f;

    const float scale = 0.125f;  // 1/sqrt(64)
    int r1 = lid >> 2;
    int a_r = lid & 15, a_h = lid >> 4;
    int b_n = ((lid >> 4) << 3) + (lid & 7), b_h = (lid >> 3) & 1;

    int nkb = 2 * qb + 2;
    for (int kb = 0; kb < nkb; kb++) {
        __syncthreads();
#pragma unroll
        for (int i = 0; i < 2; i++) {
            int c = tid + i * 256;
            int r = c >> 3, ch = c & 7;
            u32 so = SWZ128((u32)(r * 128 + ch * 16));
            size_t gk = (size_t)(b * SEQ + kb * ABK + r) * EMB + h * HD + ch * 8;
            size_t gv = ((size_t)((b * NH + h) * HD) + r) * SEQ + kb * ABK + ch * 8;
            *(uint4*)(smc + OKH + so) = *(const uint4*)(kh_ + gk);
            *(uint4*)(smc + OKL + so) = *(const uint4*)(kl_ + gk);
            *(uint4*)(smc + OVH + so) = *(const uint4*)(vth_ + gv);
            *(uint4*)(smc + OVL + so) = *(const uint4*)(vtl_ + gv);
        }
        __syncthreads();

        if (kb * ABK > warp_row + 15) continue;   // fully-masked warp tile

        // ---- S = Q K^T (hi/lo, 3 passes) ----
        float s[8][4];
#pragma unroll
        for (int nt = 0; nt < 8; nt++)
#pragma unroll
            for (int e = 0; e < 4; e++) s[nt][e] = 0.f;

#pragma unroll
        for (int kc = 0; kc < 4; kc++) {
            u32 af[4], bhf[8][2], blf[8][2];
            u32 arow = (u32)((wid * 16 + a_r) * 128 + (kc * 2 + a_h) * 16);
            ldsm_x4(af[0], af[1], af[2], af[3], sb + OQH + SWZ128(arow));
#pragma unroll
            for (int g = 0; g < 4; g++) {
                int n = g * 16 + b_n;
                u32 off = SWZ128((u32)(n * 128 + (kc * 2 + b_h) * 16));
                ldsm_x4(bhf[g * 2][0], bhf[g * 2][1],
                        bhf[g * 2 + 1][0], bhf[g * 2 + 1][1], sb + OKH + off);
                ldsm_x4(blf[g * 2][0], blf[g * 2][1],
                        blf[g * 2 + 1][0], blf[g * 2 + 1][1], sb + OKL + off);
            }
#pragma unroll
            for (int nt = 0; nt < 8; nt++) mma_bf16(s[nt], af, bhf[nt]);
#pragma unroll
            for (int nt = 0; nt < 8; nt++) mma_bf16(s[nt], af, blf[nt]);
            ldsm_x4(af[0], af[1], af[2], af[3], sb + OQL + SWZ128(arow));
#pragma unroll
            for (int nt = 0; nt < 8; nt++) mma_bf16(s[nt], af, bhf[nt]);
        }

        // ---- scale + causal mask ----
        bool needmask = (kb * ABK + ABK - 1 > warp_row);
#pragma unroll
        for (int nt = 0; nt < 8; nt++) {
#pragma unroll
            for (int e = 0; e < 4; e++) {
                s[nt][e] *= scale;
                if (needmask) {
                    int row = warp_row + r1 + ((e >> 1) << 3);
                    int col = kb * ABK + nt * 8 + (lid & 3) * 2 + (e & 1);
                    if (col > row) s[nt][e] = -INFINITY;
                }
            }
        }

        // ---- online softmax (rows r1, r1+8) ----
#pragma unroll
        for (int half = 0; half < 2; half++) {
            float mx = -INFINITY;
#pragma unroll
            for (int nt = 0; nt < 8; nt++)
                mx = fmaxf(mx, fmaxf(s[nt][half * 2], s[nt][half * 2 + 1]));
            mx = fmaxf(mx, __shfl_xor_sync(0xffffffffu, mx, 1));
            mx = fmaxf(mx, __shfl_xor_sync(0xffffffffu, mx, 2));
            float m_new = fmaxf(m_i[half], mx);
            float corr = __expf(m_i[half] - m_new);
            m_i[half] = m_new;
            float rs = 0.f;
#pragma unroll
            for (int nt = 0; nt < 8; nt++) {
                float p0 = __expf(s[nt][half * 2] - m_new);
                float p1 = __expf(s[nt][half * 2 + 1] - m_new);
                s[nt][half * 2] = p0;
                s[nt][half * 2 + 1] = p1;
                rs += p0 + p1;
            }
            rs += __shfl_xor_sync(0xffffffffu, rs, 1);
            rs += __shfl_xor_sync(0xffffffffu, rs, 2);
            l_i[half] = l_i[half] * corr + rs;
#pragma unroll
            for (int nt = 0; nt < 8; nt++) {
                o[nt][half * 2] *= corr;
                o[nt][half * 2 + 1] *= corr;
            }
        }

        // ---- O += P V (hi/lo, 3 passes); P repacked in-register ----
#pragma unroll
        for (int kc = 0; kc < 4; kc++) {
            u32 ph[4], pl[4];
            pack_hl(s[2 * kc][0], s[2 * kc][1], ph[0], pl[0]);
            pack_hl(s[2 * kc][2], s[2 * kc][3], ph[1], pl[1]);
            pack_hl(s[2 * kc + 1][0], s[2 * kc + 1][1], ph[2], pl[2]);
            pack_hl(s[2 * kc + 1][2], s[2 * kc + 1][3], ph[3], pl[3]);

            u32 bvh[8][2], bvl[8][2];
#pragma unroll
            for (int g = 0; g < 4; g++) {
                int n = g * 16 + b_n;
                u32 off = SWZ128((u32)(n * 128 + (kc * 2 + b_h) * 16));
                ldsm_x4(bvh[g * 2][0], bvh[g * 2][1],
                        bvh[g * 2 + 1][0], bvh[g * 2 + 1][1], sb + OVH + off);
                ldsm_x4(bvl[g * 2][0], bvl[g * 2][1],
                        bvl[g * 2 + 1][0], bvl[g * 2 + 1][1], sb + OVL + off);
            }
#pragma unroll
            for (int nt = 0; nt < 8; nt++) mma_bf16(o[nt], ph, bvh[nt]);
#pragma unroll
            for (int nt = 0; nt < 8; nt++) mma_bf16(o[nt], ph, bvl[nt]);
#pragma unroll
            for (int nt = 0; nt < 8; nt++) mma_bf16(o[nt], pl, bvh[nt]);
        }
    }

    // ---- epilogue: normalize, split to hi/lo bf16, store ----
#pragma unroll
    for (int half = 0; half < 2; half++) {
        float inv = 1.f / l_i[half];
        int row = warp_row + r1 + half * 8;
        size_t base = (size_t)(b * SEQ + row) * EMB + h * HD;
#pragma unroll
        for (int nt = 0; nt < 8; nt++) {
            int col = nt * 8 + (lid & 3) * 2;
            float v0 = o[nt][half * 2] * inv;
            float v1 = o[nt][half * 2 + 1] * inv;
            u32 hi, lo;
            pack_hl(v0, v1, hi, lo);
            *(u32*)&aoh[base + col] = hi;
            *(u32*)&aol[base + col] = lo;
        }
    }
}

// ---------------------------------------------------------------------------
// Launch
// ---------------------------------------------------------------------------
extern "C" void kernel_launch(void* const* d_in, const int* in_sizes, int n_in,
                              void* d_out, int out_size)
{
    const float* x  = (const float*)d_in[0];
    const float* Wq = (const float*)d_in[1];
    const float* bq = (const float*)d_in[2];
    const float* Wk = (const float*)d_in[3];
    const float* bk = (const float*)d_in[4];
    const float* Wv = (const float*)d_in[5];
    const float* bv = (const float*)d_in[6];
    const float* Wo = (const float*)d_in[7];
    const float* bo = (const float*)d_in[8];
    float* out = (float*)d_out;

    __nv_bfloat16 *ah, *al, *bh, *bl, *qh, *ql, *kh, *kl, *vh, *vl, *vth, *vtl;
    cudaGetSymbolAddress((void**)&ah, g_ah);
    cudaGetSymbolAddress((void**)&al, g_al);
    cudaGetSymbolAddress((void**)&bh, g_bh);
    cudaGetSymbolAddress((void**)&bl, g_bl);
    cudaGetSymbolAddress((void**)&qh, g_qh);
    cudaGetSymbolAddress((void**)&ql, g_ql);
    cudaGetSymbolAddress((void**)&kh, g_kh);
    cudaGetSymbolAddress((void**)&kl, g_kl);
    cudaGetSymbolAddress((void**)&vh, g_vh);
    cudaGetSymbolAddress((void**)&vl, g_vl);
    cudaGetSymbolAddress((void**)&vth, g_vth);
    cudaGetSymbolAddress((void**)&vtl, g_vtl);

    cudaFuncSetAttribute(flash_attn_tc,
                         cudaFuncAttributeMaxDynamicSharedMemorySize, ASMEM);

    dim3 ct(32, 8);
    dim3 cg(EMB / 32, EMB / 32);
    int n4 = MROWS * EMB / 4;
    dim3 ggrid(EMB / 128, MROWS / 128);
    dim3 vtgrid(SEQ / 32, BSZ * NH * 2);
    dim3 agrid(SEQ / ABQ, NH, BSZ);  // (16, 32, 2)

    // split x
    conv_rows<<<(n4 + 255) / 256, 256>>>(x, ah, al, n4);

    // QKV projections -> bf16 hi/lo directly
    conv_T<<<cg, ct>>>(Wq, bh, bl);
    gemm_mma<<<ggrid, 256>>>(ah, al, bh, bl, bq, NULL, qh, ql, MROWS, EMB, EMB);
    conv_T<<<cg, ct>>>(Wk, bh, bl);
    gemm_mma<<<ggrid, 256>>>(ah, al, bh, bl, bk, NULL, kh, kl, MROWS, EMB, EMB);
    conv_T<<<cg, ct>>>(Wv, bh, bl);
    gemm_mma<<<ggrid, 256>>>(ah, al, bh, bl, bv, NULL, vh, vl, MROWS, EMB, EMB);
    conv_vt<<<vtgrid, ct>>>(vh, vl, vth, vtl);

    // attention -> hi/lo into ah/al (x-split no longer needed)
    flash_attn_tc<<<agrid, 256, ASMEM>>>(qh, ql, kh, kl, vth, vtl, ah, al);

    // output projection (fp32 out)
    conv_T<<<cg, ct>>>(Wo, bh, bl);
    gemm_mma<<<ggrid, 256>>>(ah, al, bh, bl, bo, out, NULL, NULL, MROWS, EMB, EMB);
}

// round 7
// speedup vs baseline: 3.4775x; 1.2421x over previous
#include <cuda_runtime.h>
#include <cuda_bf16.h>
#include <cstdint>
#include <math.h>

typedef unsigned int u32;
typedef unsigned long long u64;
typedef unsigned short u16;

#define BSZ 2
#define SEQ 2048
#define EMB 2048
#define NH 32
#define HD 64
#define MROWS (BSZ*SEQ)

// ---------------------------------------------------------------------------
// Scratch (device globals: allocation-free per harness rules)
// ---------------------------------------------------------------------------
__device__ __align__(16) __nv_bfloat16 g_ah[(size_t)MROWS * EMB];
__device__ __align__(16) __nv_bfloat16 g_al[(size_t)MROWS * EMB];
__device__ __align__(16) __nv_bfloat16 g_bh[(size_t)EMB * EMB];   // W^T hi
__device__ __align__(16) __nv_bfloat16 g_bl[(size_t)EMB * EMB];   // W^T lo
__device__ __align__(16) __nv_bfloat16 g_qh[(size_t)MROWS * EMB];
__device__ __align__(16) __nv_bfloat16 g_ql[(size_t)MROWS * EMB];
__device__ __align__(16) __nv_bfloat16 g_kh[(size_t)MROWS * EMB];
__device__ __align__(16) __nv_bfloat16 g_kl[(size_t)MROWS * EMB];
__device__ __align__(16) __nv_bfloat16 g_vh[(size_t)MROWS * EMB];
__device__ __align__(16) __nv_bfloat16 g_vl[(size_t)MROWS * EMB];
__device__ __align__(16) __nv_bfloat16 g_vth[(size_t)MROWS * EMB]; // V^T per (b,h)
__device__ __align__(16) __nv_bfloat16 g_vtl[(size_t)MROWS * EMB];

// ---------------------------------------------------------------------------
// Warp-MMA / cp.async helpers (baseline PTX: works on plain sm_103 target)
// ---------------------------------------------------------------------------
__device__ __forceinline__ u32 smem_u32(const void* p) {
    u32 a;
    asm("{ .reg .u64 t; cvta.to.shared.u64 t, %1; cvt.u32.u64 %0, t; }"
        : "=r"(a) : "l"(p));
    return a;
}
__device__ __forceinline__ void ldsm_x4(u32& r0, u32& r1, u32& r2, u32& r3,
                                        u32 addr) {
    asm volatile("ldmatrix.sync.aligned.m8n8.x4.shared.b16 {%0,%1,%2,%3}, [%4];"
                 : "=r"(r0), "=r"(r1), "=r"(r2), "=r"(r3) : "r"(addr));
}
__device__ __forceinline__ void mma_bf16(float* d, const u32* a, const u32* b) {
    asm volatile(
        "mma.sync.aligned.m16n8k16.row.col.f32.bf16.bf16.f32 "
        "{%0,%1,%2,%3}, {%4,%5,%6,%7}, {%8,%9}, {%0,%1,%2,%3};"
        : "+f"(d[0]), "+f"(d[1]), "+f"(d[2]), "+f"(d[3])
        : "r"(a[0]), "r"(a[1]), "r"(a[2]), "r"(a[3]), "r"(b[0]), "r"(b[1]));
}
__device__ __forceinline__ void cp16(u32 dst, const void* src) {
    asm volatile("cp.async.cg.shared.global [%0], [%1], 16;"
                 :: "r"(dst), "l"(src) : "memory");
}
#define CP_COMMIT() asm volatile("cp.async.commit_group;" ::: "memory")
#define CP_WAIT(n)  asm volatile("cp.async.wait_group %0;" :: "n"(n) : "memory")

// pack two fp32 -> bf16x2 (lo = x0), plus bf16x2 of the residuals
__device__ __forceinline__ void pack_hl(float x0, float x1, u32& hi, u32& lo) {
    asm("cvt.rn.bf16x2.f32 %0, %1, %2;" : "=r"(hi) : "f"(x1), "f"(x0));
    float h0 = __uint_as_float(hi << 16);
    float h1 = __uint_as_float(hi & 0xFFFF0000u);
    float r0 = x0 - h0, r1 = x1 - h1;
    asm("cvt.rn.bf16x2.f32 %0, %1, %2;" : "=r"(lo) : "f"(r1), "f"(r0));
}
#define SWZ64(o)  ((o) ^ (((o) >> 3) & 0x30))
#define SWZ128(o) ((o) ^ (((o) >> 3) & 0x70))

// ---------------------------------------------------------------------------
// Conversion kernels
// ---------------------------------------------------------------------------
__global__ void conv_rows(const float* __restrict__ X,
                          __nv_bfloat16* __restrict__ H,
                          __nv_bfloat16* __restrict__ L, int n4)
{
    int i = blockIdx.x * blockDim.x + threadIdx.x;
    if (i >= n4) return;
    float4 v = ((const float4*)X)[i];
    u32 h0, l0, h1, l1;
    pack_hl(v.x, v.y, h0, l0);
    pack_hl(v.z, v.w, h1, l1);
    ((uint2*)H)[i] = make_uint2(h0, h1);
    ((uint2*)L)[i] = make_uint2(l0, l1);
}

// W[K,N] fp32 -> W^T hi/lo bf16 [N,K]
__global__ void conv_T(const float* __restrict__ W,
                       __nv_bfloat16* __restrict__ Th,
                       __nv_bfloat16* __restrict__ Tl)
{
    __shared__ float t[32][33];
    int n0 = blockIdx.x * 32, k0 = blockIdx.y * 32;
    int x = threadIdx.x, y = threadIdx.y;  // 32 x 8
#pragma unroll
    for (int r = 0; r < 32; r += 8)
        t[y + r][x] = W[(size_t)(k0 + y + r) * EMB + n0 + x];
    __syncthreads();
#pragma unroll
    for (int r = 0; r < 32; r += 8) {
        float v = t[x][y + r];
        __nv_bfloat16 h = __float2bfloat16(v);
        size_t o = (size_t)(n0 + y + r) * EMB + k0 + x;
        Th[o] = h;
        Tl[o] = __float2bfloat16(v - __bfloat162float(h));
    }
}

// Vh/Vl [token][h*64+d] -> VTh/VTl [(b*NH+h)*64+d][seq]
__global__ void conv_vt(const __nv_bfloat16* __restrict__ Vh,
                        const __nv_bfloat16* __restrict__ Vl,
                        __nv_bfloat16* __restrict__ VTh,
                        __nv_bfloat16* __restrict__ VTl)
{
    __shared__ u16 th[32][33], tl[32][33];
    int s0 = blockIdx.x * 32;
    int d0 = (blockIdx.y & 1) * 32;
    int hh = (blockIdx.y >> 1) & 31;
    int b  = blockIdx.y >> 6;
    int x = threadIdx.x, y = threadIdx.y;  // 32 x 8
#pragma unroll
    for (int r = 0; r < 32; r += 8) {
        size_t g = (size_t)(b * SEQ + s0 + y + r) * EMB + hh * HD + d0 + x;
        th[y + r][x] = *(const u16*)(Vh + g);
        tl[y + r][x] = *(const u16*)(Vl + g);
    }
    __syncthreads();
#pragma unroll
    for (int r = 0; r < 32; r += 8) {
        size_t o = ((size_t)((b * NH + hh) * HD) + d0 + y + r) * SEQ + s0 + x;
        *(u16*)(VTh + o) = th[x][y + r];
        *(u16*)(VTl + o) = tl[x][y + r];
    }
}

// ---------------------------------------------------------------------------
// Tensor-core GEMM via mma.sync (bf16 hi/lo split, fp32 accumulate),
// cp.async 2-stage pipeline.
//   out = A @ W + bias,  A as Ah/Al [M,K],  W as Bh/Bl [N,K] (=W^T).
// If C != null: write fp32 C. Else: write bf16 hi/lo to H/L.
// Stage layout (32 KB): AH 0, AL 8192, BH 16384, BL 24576.
// ---------------------------------------------------------------------------
#define BKC 32
#define GSTG 32768
#define GSMEM (2 * GSTG)

__global__ __launch_bounds__(256, 2)
void gemm_mma(const __nv_bfloat16* __restrict__ Ah,
              const __nv_bfloat16* __restrict__ Al,
              const __nv_bfloat16* __restrict__ Bh,
              const __nv_bfloat16* __restrict__ Bl,
              const float* __restrict__ bias,
              float* __restrict__ C,
              __nv_bfloat16* __restrict__ H,
              __nv_bfloat16* __restrict__ L,
              int M, int N, int K)
{
    extern __shared__ char smg[];
    u32 sb = smem_u32(smg);

    int tid = threadIdx.x;
    int wid = tid / 32, lid = tid % 32;
    int wm = wid / 4, wn = wid % 4;        // warp grid 2 x 4
    int bm = blockIdx.y * 128, bn = blockIdx.x * 128;

    float acc[4][4][4];
#pragma unroll
    for (int mt = 0; mt < 4; mt++)
#pragma unroll
        for (int nt = 0; nt < 4; nt++)
#pragma unroll
            for (int e = 0; e < 4; e++) acc[mt][nt][e] = 0.f;

    int a_r = (lid & 15);
    int a_h = (lid >> 4);
    int b_n = ((lid >> 4) << 3) + (lid & 7);
    int b_h = ((lid >> 3) & 1);

    // per-thread load coordinates
    int l_row[2], l_ch[2];
#pragma unroll
    for (int cc = 0; cc < 2; cc++) {
        int c = tid + cc * 256;
        l_row[cc] = c >> 2;
        l_ch[cc] = c & 3;
    }

#define GEMM_ISSUE(stage, k0)                                                  \
    do {                                                                       \
        u32 base_ = sb + (stage) * GSTG;                                       \
        _Pragma("unroll")                                                      \
        for (int cc = 0; cc < 2; cc++) {                                       \
            int row = l_row[cc], ch = l_ch[cc];                                \
            u32 so = SWZ64((u32)(row * 64 + ch * 16));                         \
            size_t ga = (size_t)(bm + row) * K + (k0) + ch * 8;                \
            size_t gb = (size_t)(bn + row) * K + (k0) + ch * 8;                \
            cp16(base_ + so, Ah + ga);                                         \
            cp16(base_ + 8192 + so, Al + ga);                                  \
            cp16(base_ + 16384 + so, Bh + gb);                                 \
            cp16(base_ + 24576 + so, Bl + gb);                                 \
        }                                                                      \
        CP_COMMIT();                                                           \
    } while (0)

    int niter = K / BKC;
    GEMM_ISSUE(0, 0);

    for (int it = 0; it < niter; it++) {
        if (it + 1 < niter) {
            GEMM_ISSUE((it + 1) & 1, (it + 1) * BKC);
            CP_WAIT(1);
        } else {
            CP_WAIT(0);
        }
        __syncthreads();

        u32 baseAh = sb + (it & 1) * GSTG;
        u32 baseAl = baseAh + 8192;
        u32 baseBh = baseAh + 16384;
        u32 baseBl = baseAh + 24576;

#pragma unroll
        for (int ks = 0; ks < 2; ks++) {
            u32 af[4][4], bhf[4][2], blf[4][2];
#pragma unroll
            for (int mt = 0; mt < 4; mt++) {
                int r = wm * 64 + mt * 16 + a_r;
                u32 addr = baseAh + SWZ64((u32)(r * 64 + (ks * 2 + a_h) * 16));
                ldsm_x4(af[mt][0], af[mt][1], af[mt][2], af[mt][3], addr);
            }
#pragma unroll
            for (int np = 0; np < 2; np++) {
                int n = wn * 32 + np * 16 + b_n;
                u32 off = SWZ64((u32)(n * 64 + (ks * 2 + b_h) * 16));
                ldsm_x4(bhf[np * 2][0], bhf[np * 2][1],
                        bhf[np * 2 + 1][0], bhf[np * 2 + 1][1], baseBh + off);
                ldsm_x4(blf[np * 2][0], blf[np * 2][1],
                        blf[np * 2 + 1][0], blf[np * 2 + 1][1], baseBl + off);
            }
#pragma unroll
            for (int mt = 0; mt < 4; mt++)
#pragma unroll
                for (int nt = 0; nt < 4; nt++)
                    mma_bf16(acc[mt][nt], af[mt], bhf[nt]);
#pragma unroll
            for (int mt = 0; mt < 4; mt++)
#pragma unroll
                for (int nt = 0; nt < 4; nt++)
                    mma_bf16(acc[mt][nt], af[mt], blf[nt]);
#pragma unroll
            for (int mt = 0; mt < 4; mt++) {
                int r = wm * 64 + mt * 16 + a_r;
                u32 addr = baseAl + SWZ64((u32)(r * 64 + (ks * 2 + a_h) * 16));
                ldsm_x4(af[mt][0], af[mt][1], af[mt][2], af[mt][3], addr);
            }
#pragma unroll
            for (int mt = 0; mt < 4; mt++)
#pragma unroll
                for (int nt = 0; nt < 4; nt++)
                    mma_bf16(acc[mt][nt], af[mt], bhf[nt]);
        }
        __syncthreads();   // stage (it&1) free for reuse at iter it+1
    }

    int rr = lid >> 2, cc2 = (lid & 3) * 2;
#pragma unroll
    for (int mt = 0; mt < 4; mt++) {
        int r0 = bm + wm * 64 + mt * 16 + rr;
#pragma unroll
        for (int nt = 0; nt < 4; nt++) {
            int col = bn + wn * 32 + nt * 8 + cc2;
            float b0 = bias[col], b1 = bias[col + 1];
            float v00 = acc[mt][nt][0] + b0, v01 = acc[mt][nt][1] + b1;
            float v10 = acc[mt][nt][2] + b0, v11 = acc[mt][nt][3] + b1;
            if (C) {
                *(float2*)&C[(size_t)r0 * N + col] = make_float2(v00, v01);
                *(float2*)&C[(size_t)(r0 + 8) * N + col] = make_float2(v10, v11);
            } else {
                u32 hi, lo;
                pack_hl(v00, v01, hi, lo);
                *(u32*)&H[(size_t)r0 * N + col] = hi;
                *(u32*)&L[(size_t)r0 * N + col] = lo;
                pack_hl(v10, v11, hi, lo);
                *(u32*)&H[(size_t)(r0 + 8) * N + col] = hi;
                *(u32*)&L[(size_t)(r0 + 8) * N + col] = lo;
            }
        }
    }
}

// ---------------------------------------------------------------------------
// Tensor-core causal flash attention (bf16 hi/lo, fp32 softmax),
// cp.async 2-stage K/V pipeline.
// RoPE mathematically eliminated (head-only rotation; q.k invariant).
// CTA: 128 q rows, 8 warps (warp = 16 q rows x full 64-col kv tile).
// SMEM: Q (32 KB) + 2 stages x (KH,KL,VH,VL = 32 KB).
// ---------------------------------------------------------------------------
#define ABQ 128
#define ABK 64
#define OQH 0
#define OQL 16384
#define AKV 32768
#define ASTG 32768
#define ASMEM (AKV + 2 * ASTG)

__global__ __launch_bounds__(256)
void flash_attn_tc(const __nv_bfloat16* __restrict__ qh_,
                   const __nv_bfloat16* __restrict__ ql_,
                   const __nv_bfloat16* __restrict__ kh_,
                   const __nv_bfloat16* __restrict__ kl_,
                   const __nv_bfloat16* __restrict__ vth_,
                   const __nv_bfloat16* __restrict__ vtl_,
                   __nv_bfloat16* __restrict__ aoh,
                   __nv_bfloat16* __restrict__ aol)
{
    extern __shared__ char smc[];
    u32 sb = smem_u32(smc);
    int tid = threadIdx.x, wid = tid / 32, lid = tid % 32;
    int qb = blockIdx.x, h = blockIdx.y, b = blockIdx.z;
    int q0 = qb * ABQ;
    int warp_row = q0 + wid * 16;

    // Load Q tile (128x64 hi/lo), SW128 rows
#pragma unroll
    for (int i = 0; i < 4; i++) {
        int c = tid + i * 256;
        int r = c >> 3, ch = c & 7;
        u32 so = SWZ128((u32)(r * 128 + ch * 16));
        size_t g = (size_t)(b * SEQ + q0 + r) * EMB + h * HD + ch * 8;
        *(uint4*)(smc + OQH + so) = *(const uint4*)(qh_ + g);
        *(uint4*)(smc + OQL + so) = *(const uint4*)(ql_ + g);
    }

    // per-thread K/V load coordinates
    int v_r[2], v_ch[2];
#pragma unroll
    for (int i = 0; i < 2; i++) {
        int c = tid + i * 256;
        v_r[i] = c >> 3;
        v_ch[i] = c & 7;
    }

#define ATTN_ISSUE(stage, kb)                                                  \
    do {                                                                       \
        u32 base_ = sb + AKV + (stage) * ASTG;                                 \
        _Pragma("unroll")                                                      \
        for (int i = 0; i < 2; i++) {                                          \
            int r = v_r[i], ch = v_ch[i];                                      \
            u32 so = SWZ128((u32)(r * 128 + ch * 16));                         \
            size_t gk = (size_t)(b * SEQ + (kb) * ABK + r) * EMB + h * HD + ch * 8; \
            size_t gv = ((size_t)((b * NH + h) * HD) + r) * SEQ + (kb) * ABK + ch * 8; \
            cp16(base_ + so, kh_ + gk);                                        \
            cp16(base_ + 8192 + so, kl_ + gk);                                 \
            cp16(base_ + 16384 + so, vth_ + gv);                               \
            cp16(base_ + 24576 + so, vtl_ + gv);                               \
        }                                                                      \
        CP_COMMIT();                                                           \
    } while (0)

    float m_i[2], l_i[2], o[8][4];
    m_i[0] = m_i[1] = -INFINITY;
    l_i[0] = l_i[1] = 0.f;
#pragma unroll
    for (int nt = 0; nt < 8; nt++)
#pragma unroll
        for (int e = 0; e < 4; e++) o[nt][e] = 0.f;

    const float scale = 0.125f;  // 1/sqrt(64)
    int r1 = lid >> 2;
    int a_r = lid & 15, a_h = lid >> 4;
    int b_n = ((lid >> 4) << 3) + (lid & 7), b_h = (lid >> 3) & 1;

    int nkb = 2 * qb + 2;
    ATTN_ISSUE(0, 0);

    for (int kb = 0; kb < nkb; kb++) {
        if (kb + 1 < nkb) {
            ATTN_ISSUE((kb + 1) & 1, kb + 1);
            CP_WAIT(1);
        } else {
            CP_WAIT(0);
        }
        __syncthreads();

        if (kb * ABK <= warp_row + 15) {   // not fully masked
            u32 bk = sb + AKV + (kb & 1) * ASTG;
            u32 okh = bk, okl = bk + 8192, ovh = bk + 16384, ovl = bk + 24576;

            // ---- S = Q K^T (hi/lo, 3 passes) ----
            float s[8][4];
#pragma unroll
            for (int nt = 0; nt < 8; nt++)
#pragma unroll
                for (int e = 0; e < 4; e++) s[nt][e] = 0.f;

#pragma unroll
            for (int kc = 0; kc < 4; kc++) {
                u32 af[4], bhf[8][2], blf[8][2];
                u32 arow = (u32)((wid * 16 + a_r) * 128 + (kc * 2 + a_h) * 16);
                ldsm_x4(af[0], af[1], af[2], af[3], sb + OQH + SWZ128(arow));
#pragma unroll
                for (int g = 0; g < 4; g++) {
                    int n = g * 16 + b_n;
                    u32 off = SWZ128((u32)(n * 128 + (kc * 2 + b_h) * 16));
                    ldsm_x4(bhf[g * 2][0], bhf[g * 2][1],
                            bhf[g * 2 + 1][0], bhf[g * 2 + 1][1], okh + off);
                    ldsm_x4(blf[g * 2][0], blf[g * 2][1],
                            blf[g * 2 + 1][0], blf[g * 2 + 1][1], okl + off);
                }
#pragma unroll
                for (int nt = 0; nt < 8; nt++) mma_bf16(s[nt], af, bhf[nt]);
#pragma unroll
                for (int nt = 0; nt < 8; nt++) mma_bf16(s[nt], af, blf[nt]);
                ldsm_x4(af[0], af[1], af[2], af[3], sb + OQL + SWZ128(arow));
#pragma unroll
                for (int nt = 0; nt < 8; nt++) mma_bf16(s[nt], af, bhf[nt]);
            }

            // ---- scale + causal mask ----
            bool needmask = (kb * ABK + ABK - 1 > warp_row);
#pragma unroll
            for (int nt = 0; nt < 8; nt++) {
#pragma unroll
                for (int e = 0; e < 4; e++) {
                    s[nt][e] *= scale;
                    if (needmask) {
                        int row = warp_row + r1 + ((e >> 1) << 3);
                        int col = kb * ABK + nt * 8 + (lid & 3) * 2 + (e & 1);
                        if (col > row) s[nt][e] = -INFINITY;
                    }
                }
            }

            // ---- online softmax (rows r1, r1+8) ----
#pragma unroll
            for (int half = 0; half < 2; half++) {
                float mx = -INFINITY;
#pragma unroll
                for (int nt = 0; nt < 8; nt++)
                    mx = fmaxf(mx, fmaxf(s[nt][half * 2], s[nt][half * 2 + 1]));
                mx = fmaxf(mx, __shfl_xor_sync(0xffffffffu, mx, 1));
                mx = fmaxf(mx, __shfl_xor_sync(0xffffffffu, mx, 2));
                float m_new = fmaxf(m_i[half], mx);
                float corr = __expf(m_i[half] - m_new);
                m_i[half] = m_new;
                float rs = 0.f;
#pragma unroll
                for (int nt = 0; nt < 8; nt++) {
                    float p0 = __expf(s[nt][half * 2] - m_new);
                    float p1 = __expf(s[nt][half * 2 + 1] - m_new);
                    s[nt][half * 2] = p0;
                    s[nt][half * 2 + 1] = p1;
                    rs += p0 + p1;
                }
                rs += __shfl_xor_sync(0xffffffffu, rs, 1);
                rs += __shfl_xor_sync(0xffffffffu, rs, 2);
                l_i[half] = l_i[half] * corr + rs;
#pragma unroll
                for (int nt = 0; nt < 8; nt++) {
                    o[nt][half * 2] *= corr;
                    o[nt][half * 2 + 1] *= corr;
                }
            }

            // ---- O += P V (hi/lo, 3 passes); P repacked in-register ----
#pragma unroll
            for (int kc = 0; kc < 4; kc++) {
                u32 ph[4], pl[4];
                pack_hl(s[2 * kc][0], s[2 * kc][1], ph[0], pl[0]);
                pack_hl(s[2 * kc][2], s[2 * kc][3], ph[1], pl[1]);
                pack_hl(s[2 * kc + 1][0], s[2 * kc + 1][1], ph[2], pl[2]);
                pack_hl(s[2 * kc + 1][2], s[2 * kc + 1][3], ph[3], pl[3]);

                u32 bvh[8][2], bvl[8][2];
#pragma unroll
                for (int g = 0; g < 4; g++) {
                    int n = g * 16 + b_n;
                    u32 off = SWZ128((u32)(n * 128 + (kc * 2 + b_h) * 16));
                    ldsm_x4(bvh[g * 2][0], bvh[g * 2][1],
                            bvh[g * 2 + 1][0], bvh[g * 2 + 1][1], ovh + off);
                    ldsm_x4(bvl[g * 2][0], bvl[g * 2][1],
                            bvl[g * 2 + 1][0], bvl[g * 2 + 1][1], ovl + off);
                }
#pragma unroll
                for (int nt = 0; nt < 8; nt++) mma_bf16(o[nt], ph, bvh[nt]);
#pragma unroll
                for (int nt = 0; nt < 8; nt++) mma_bf16(o[nt], ph, bvl[nt]);
#pragma unroll
                for (int nt = 0; nt < 8; nt++) mma_bf16(o[nt], pl, bvh[nt]);
            }
        }
        __syncthreads();   // stage (kb&1) free for reuse
    }

    // ---- epilogue: normalize, split to hi/lo bf16, store ----
#pragma unroll
    for (int half = 0; half < 2; half++) {
        float inv = 1.f / l_i[half];
        int row = warp_row + r1 + half * 8;
        size_t base = (size_t)(b * SEQ + row) * EMB + h * HD;
#pragma unroll
        for (int nt = 0; nt < 8; nt++) {
            int col = nt * 8 + (lid & 3) * 2;
            float v0 = o[nt][half * 2] * inv;
            float v1 = o[nt][half * 2 + 1] * inv;
            u32 hi, lo;
            pack_hl(v0, v1, hi, lo);
            *(u32*)&aoh[base + col] = hi;
            *(u32*)&aol[base + col] = lo;
        }
    }
}

// ---------------------------------------------------------------------------
// Launch
// ---------------------------------------------------------------------------
extern "C" void kernel_launch(void* const* d_in, const int* in_sizes, int n_in,
                              void* d_out, int out_size)
{
    const float* x  = (const float*)d_in[0];
    const float* Wq = (const float*)d_in[1];
    const float* bq = (const float*)d_in[2];
    const float* Wk = (const float*)d_in[3];
    const float* bk = (const float*)d_in[4];
    const float* Wv = (const float*)d_in[5];
    const float* bv = (const float*)d_in[6];
    const float* Wo = (const float*)d_in[7];
    const float* bo = (const float*)d_in[8];
    float* out = (float*)d_out;

    __nv_bfloat16 *ah, *al, *bh, *bl, *qh, *ql, *kh, *kl, *vh, *vl, *vth, *vtl;
    cudaGetSymbolAddress((void**)&ah, g_ah);
    cudaGetSymbolAddress((void**)&al, g_al);
    cudaGetSymbolAddress((void**)&bh, g_bh);
    cudaGetSymbolAddress((void**)&bl, g_bl);
    cudaGetSymbolAddress((void**)&qh, g_qh);
    cudaGetSymbolAddress((void**)&ql, g_ql);
    cudaGetSymbolAddress((void**)&kh, g_kh);
    cudaGetSymbolAddress((void**)&kl, g_kl);
    cudaGetSymbolAddress((void**)&vh, g_vh);
    cudaGetSymbolAddress((void**)&vl, g_vl);
    cudaGetSymbolAddress((void**)&vth, g_vth);
    cudaGetSymbolAddress((void**)&vtl, g_vtl);

    cudaFuncSetAttribute(gemm_mma,
                         cudaFuncAttributeMaxDynamicSharedMemorySize, GSMEM);
    cudaFuncSetAttribute(flash_attn_tc,
                         cudaFuncAttributeMaxDynamicSharedMemorySize, ASMEM);

    dim3 ct(32, 8);
    dim3 cg(EMB / 32, EMB / 32);
    int n4 = MROWS * EMB / 4;
    dim3 ggrid(EMB / 128, MROWS / 128);
    dim3 vtgrid(SEQ / 32, BSZ * NH * 2);
    dim3 agrid(SEQ / ABQ, NH, BSZ);  // (16, 32, 2)

    // split x
    conv_rows<<<(n4 + 255) / 256, 256>>>(x, ah, al, n4);

    // QKV projections -> bf16 hi/lo directly
    conv_T<<<cg, ct>>>(Wq, bh, bl);
    gemm_mma<<<ggrid, 256, GSMEM>>>(ah, al, bh, bl, bq, NULL, qh, ql, MROWS, EMB, EMB);
    conv_T<<<cg, ct>>>(Wk, bh, bl);
    gemm_mma<<<ggrid, 256, GSMEM>>>(ah, al, bh, bl, bk, NULL, kh, kl, MROWS, EMB, EMB);
    conv_T<<<cg, ct>>>(Wv, bh, bl);
    gemm_mma<<<ggrid, 256, GSMEM>>>(ah, al, bh, bl, bv, NULL, vh, vl, MROWS, EMB, EMB);
    conv_vt<<<vtgrid, ct>>>(vh, vl, vth, vtl);

    // attention -> hi/lo into ah/al (x-split no longer needed)
    flash_attn_tc<<<agrid, 256, ASMEM>>>(qh, ql, kh, kl, vth, vtl, ah, al);

    // output projection (fp32 out)
    conv_T<<<cg, ct>>>(Wo, bh, bl);
    gemm_mma<<<ggrid, 256, GSMEM>>>(ah, al, bh, bl, bo, out, NULL, NULL, MROWS, EMB, EMB);
}

// round 8
// speedup vs baseline: 3.6607x; 1.0527x over previous
#include <cuda_runtime.h>
#include <cuda_bf16.h>
#include <cstdint>
#include <math.h>

typedef unsigned int u32;
typedef unsigned long long u64;
typedef unsigned short u16;

#define BSZ 2
#define SEQ 2048
#define EMB 2048
#define NH 32
#define HD 64
#define MROWS (BSZ*SEQ)

// ---------------------------------------------------------------------------
// Scratch (device globals: allocation-free per harness rules)
// ---------------------------------------------------------------------------
__device__ __align__(16) __nv_bfloat16 g_ah[(size_t)MROWS * EMB];
__device__ __align__(16) __nv_bfloat16 g_al[(size_t)MROWS * EMB];
__device__ __align__(16) __nv_bfloat16 g_bh[(size_t)4 * EMB * EMB];  // W^T hi x4
__device__ __align__(16) __nv_bfloat16 g_bl[(size_t)4 * EMB * EMB];  // W^T lo x4
__device__ __align__(16) __nv_bfloat16 g_qh[(size_t)MROWS * EMB];
__device__ __align__(16) __nv_bfloat16 g_ql[(size_t)MROWS * EMB];
__device__ __align__(16) __nv_bfloat16 g_kh[(size_t)MROWS * EMB];
__device__ __align__(16) __nv_bfloat16 g_kl[(size_t)MROWS * EMB];
__device__ __align__(16) __nv_bfloat16 g_vh[(size_t)MROWS * EMB];
__device__ __align__(16) __nv_bfloat16 g_vl[(size_t)MROWS * EMB];
__device__ __align__(16) __nv_bfloat16 g_vth[(size_t)MROWS * EMB]; // V^T per (b,h)
__device__ __align__(16) __nv_bfloat16 g_vtl[(size_t)MROWS * EMB];

// ---------------------------------------------------------------------------
// Warp-MMA / cp.async helpers (baseline PTX: works on plain sm_103 target)
// ---------------------------------------------------------------------------
__device__ __forceinline__ u32 smem_u32(const void* p) {
    u32 a;
    asm("{ .reg .u64 t; cvta.to.shared.u64 t, %1; cvt.u32.u64 %0, t; }"
        : "=r"(a) : "l"(p));
    return a;
}
__device__ __forceinline__ void ldsm_x4(u32& r0, u32& r1, u32& r2, u32& r3,
                                        u32 addr) {
    asm volatile("ldmatrix.sync.aligned.m8n8.x4.shared.b16 {%0,%1,%2,%3}, [%4];"
                 : "=r"(r0), "=r"(r1), "=r"(r2), "=r"(r3) : "r"(addr));
}
__device__ __forceinline__ void mma_bf16(float* d, const u32* a, const u32* b) {
    asm volatile(
        "mma.sync.aligned.m16n8k16.row.col.f32.bf16.bf16.f32 "
        "{%0,%1,%2,%3}, {%4,%5,%6,%7}, {%8,%9}, {%0,%1,%2,%3};"
        : "+f"(d[0]), "+f"(d[1]), "+f"(d[2]), "+f"(d[3])
        : "r"(a[0]), "r"(a[1]), "r"(a[2]), "r"(a[3]), "r"(b[0]), "r"(b[1]));
}
__device__ __forceinline__ void cp16(u32 dst, const void* src) {
    asm volatile("cp.async.cg.shared.global [%0], [%1], 16;"
                 :: "r"(dst), "l"(src) : "memory");
}
#define CP_COMMIT() asm volatile("cp.async.commit_group;" ::: "memory")
#define CP_WAIT(n)  asm volatile("cp.async.wait_group %0;" :: "n"(n) : "memory")

// pack two fp32 -> bf16x2 (lo = x0), plus bf16x2 of the residuals
__device__ __forceinline__ void pack_hl(float x0, float x1, u32& hi, u32& lo) {
    asm("cvt.rn.bf16x2.f32 %0, %1, %2;" : "=r"(hi) : "f"(x1), "f"(x0));
    float h0 = __uint_as_float(hi << 16);
    float h1 = __uint_as_float(hi & 0xFFFF0000u);
    float r0 = x0 - h0, r1 = x1 - h1;
    asm("cvt.rn.bf16x2.f32 %0, %1, %2;" : "=r"(lo) : "f"(r1), "f"(r0));
}
#define SWZ64(o)  ((o) ^ (((o) >> 3) & 0x30))
#define SWZ128(o) ((o) ^ (((o) >> 3) & 0x70))

// ---------------------------------------------------------------------------
// Conversion kernels
// ---------------------------------------------------------------------------
__global__ void conv_rows(const float* __restrict__ X,
                          __nv_bfloat16* __restrict__ H,
                          __nv_bfloat16* __restrict__ L, int n4)
{
    int i = blockIdx.x * blockDim.x + threadIdx.x;
    if (i >= n4) return;
    float4 v = ((const float4*)X)[i];
    u32 h0, l0, h1, l1;
    pack_hl(v.x, v.y, h0, l0);
    pack_hl(v.z, v.w, h1, l1);
    ((uint2*)H)[i] = make_uint2(h0, h1);
    ((uint2*)L)[i] = make_uint2(l0, l1);
}

// All 4 weights W[K,N] fp32 -> W^T hi/lo bf16 [N,K], one launch (z selects W)
__global__ void conv_T4(const float* __restrict__ W0, const float* __restrict__ W1,
                        const float* __restrict__ W2, const float* __restrict__ W3,
                        __nv_bfloat16* __restrict__ Th,
                        __nv_bfloat16* __restrict__ Tl)
{
    __shared__ float t[32][33];
    int z = blockIdx.z;
    const float* W = (z == 0) ? W0 : (z == 1) ? W1 : (z == 2) ? W2 : W3;
    size_t zo = (size_t)z * EMB * EMB;
    int n0 = blockIdx.x * 32, k0 = blockIdx.y * 32;
    int x = threadIdx.x, y = threadIdx.y;  // 32 x 8
#pragma unroll
    for (int r = 0; r < 32; r += 8)
        t[y + r][x] = W[(size_t)(k0 + y + r) * EMB + n0 + x];
    __syncthreads();
#pragma unroll
    for (int r = 0; r < 32; r += 8) {
        float v = t[x][y + r];
        __nv_bfloat16 h = __float2bfloat16(v);
        size_t o = zo + (size_t)(n0 + y + r) * EMB + k0 + x;
        Th[o] = h;
        Tl[o] = __float2bfloat16(v - __bfloat162float(h));
    }
}

// Vh/Vl [token][h*64+d] -> VTh/VTl [(b*NH+h)*64+d][seq]
__global__ void conv_vt(const __nv_bfloat16* __restrict__ Vh,
                        const __nv_bfloat16* __restrict__ Vl,
                        __nv_bfloat16* __restrict__ VTh,
                        __nv_bfloat16* __restrict__ VTl)
{
    __shared__ u16 th[32][33], tl[32][33];
    int s0 = blockIdx.x * 32;
    int d0 = (blockIdx.y & 1) * 32;
    int hh = (blockIdx.y >> 1) & 31;
    int b  = blockIdx.y >> 6;
    int x = threadIdx.x, y = threadIdx.y;  // 32 x 8
#pragma unroll
    for (int r = 0; r < 32; r += 8) {
        size_t g = (size_t)(b * SEQ + s0 + y + r) * EMB + hh * HD + d0 + x;
        th[y + r][x] = *(const u16*)(Vh + g);
        tl[y + r][x] = *(const u16*)(Vl + g);
    }
    __syncthreads();
#pragma unroll
    for (int r = 0; r < 32; r += 8) {
        size_t o = ((size_t)((b * NH + hh) * HD) + d0 + y + r) * SEQ + s0 + x;
        *(u16*)(VTh + o) = th[x][y + r];
        *(u16*)(VTl + o) = tl[x][y + r];
    }
}

// ---------------------------------------------------------------------------
// Tensor-core GEMM via mma.sync (bf16 hi/lo split, fp32 accumulate),
// cp.async 3-stage pipeline. Handles all 4 projections via mat index:
//   mat = mat_base + blockIdx.x/16; B/bias/output selected per mat.
//   mats 0,1,2 -> bf16 hi/lo outputs (Q,K,V); mat 3 -> fp32 C (out proj).
// Stage layout (32 KB): AH 0, AL 8192, BH 16384, BL 24576.
// ---------------------------------------------------------------------------
#define BKC 32
#define GSTG 32768
#define GSMEM (3 * GSTG)

__global__ __launch_bounds__(256, 2)
void gemm_mma(const __nv_bfloat16* __restrict__ Ah,
              const __nv_bfloat16* __restrict__ Al,
              const __nv_bfloat16* __restrict__ BhAll,
              const __nv_bfloat16* __restrict__ BlAll,
              const float* __restrict__ b0, const float* __restrict__ b1,
              const float* __restrict__ b2, const float* __restrict__ b3,
              __nv_bfloat16* __restrict__ H0, __nv_bfloat16* __restrict__ L0,
              __nv_bfloat16* __restrict__ H1, __nv_bfloat16* __restrict__ L1,
              __nv_bfloat16* __restrict__ H2, __nv_bfloat16* __restrict__ L2,
              float* __restrict__ C, int mat_base, int M, int K)
{
    extern __shared__ char smg[];
    u32 sb = smem_u32(smg);
    const int N = EMB;

    int tid = threadIdx.x;
    int wid = tid / 32, lid = tid % 32;
    int wm = wid / 4, wn = wid % 4;        // warp grid 2 x 4
    int mat = mat_base + (blockIdx.x >> 4);
    int bm = blockIdx.y * 128, bn = (blockIdx.x & 15) * 128;

    const __nv_bfloat16* Bh = BhAll + (size_t)mat * EMB * EMB;
    const __nv_bfloat16* Bl = BlAll + (size_t)mat * EMB * EMB;
    const float* bias = (mat == 0) ? b0 : (mat == 1) ? b1 : (mat == 2) ? b2 : b3;

    float acc[4][4][4];
#pragma unroll
    for (int mt = 0; mt < 4; mt++)
#pragma unroll
        for (int nt = 0; nt < 4; nt++)
#pragma unroll
            for (int e = 0; e < 4; e++) acc[mt][nt][e] = 0.f;

    int a_r = (lid & 15);
    int a_h = (lid >> 4);
    int b_n = ((lid >> 4) << 3) + (lid & 7);
    int b_h = ((lid >> 3) & 1);

    int l_row[2], l_ch[2];
#pragma unroll
    for (int cc = 0; cc < 2; cc++) {
        int c = tid + cc * 256;
        l_row[cc] = c >> 2;
        l_ch[cc] = c & 3;
    }

#define GEMM_ISSUE(stage, k0)                                                  \
    do {                                                                       \
        u32 base_ = sb + (stage) * GSTG;                                       \
        _Pragma("unroll")                                                      \
        for (int cc = 0; cc < 2; cc++) {                                       \
            int row = l_row[cc], ch = l_ch[cc];                                \
            u32 so = SWZ64((u32)(row * 64 + ch * 16));                         \
            size_t ga = (size_t)(bm + row) * K + (k0) + ch * 8;                \
            size_t gb = (size_t)(bn + row) * K + (k0) + ch * 8;                \
            cp16(base_ + so, Ah + ga);                                         \
            cp16(base_ + 8192 + so, Al + ga);                                  \
            cp16(base_ + 16384 + so, Bh + gb);                                 \
            cp16(base_ + 24576 + so, Bl + gb);                                 \
        }                                                                      \
        CP_COMMIT();                                                           \
    } while (0)

    int niter = K / BKC;
    GEMM_ISSUE(0, 0);
    GEMM_ISSUE(1, BKC);

    for (int it = 0; it < niter; it++) {
        if (it + 2 < niter) {
            int st = (it + 2) % 3;
            GEMM_ISSUE(st, (it + 2) * BKC);
            CP_WAIT(2);
        } else if (it + 1 < niter) {
            CP_WAIT(1);
        } else {
            CP_WAIT(0);
        }
        __syncthreads();

        u32 baseAh = sb + (it % 3) * GSTG;
        u32 baseAl = baseAh + 8192;
        u32 baseBh = baseAh + 16384;
        u32 baseBl = baseAh + 24576;

#pragma unroll
        for (int ks = 0; ks < 2; ks++) {
            u32 af[4][4], bhf[4][2], blf[4][2];
#pragma unroll
            for (int mt = 0; mt < 4; mt++) {
                int r = wm * 64 + mt * 16 + a_r;
                u32 addr = baseAh + SWZ64((u32)(r * 64 + (ks * 2 + a_h) * 16));
                ldsm_x4(af[mt][0], af[mt][1], af[mt][2], af[mt][3], addr);
            }
#pragma unroll
            for (int np = 0; np < 2; np++) {
                int n = wn * 32 + np * 16 + b_n;
                u32 off = SWZ64((u32)(n * 64 + (ks * 2 + b_h) * 16));
                ldsm_x4(bhf[np * 2][0], bhf[np * 2][1],
                        bhf[np * 2 + 1][0], bhf[np * 2 + 1][1], baseBh + off);
                ldsm_x4(blf[np * 2][0], blf[np * 2][1],
                        blf[np * 2 + 1][0], blf[np * 2 + 1][1], baseBl + off);
            }
#pragma unroll
            for (int mt = 0; mt < 4; mt++)
#pragma unroll
                for (int nt = 0; nt < 4; nt++)
                    mma_bf16(acc[mt][nt], af[mt], bhf[nt]);
#pragma unroll
            for (int mt = 0; mt < 4; mt++)
#pragma unroll
                for (int nt = 0; nt < 4; nt++)
                    mma_bf16(acc[mt][nt], af[mt], blf[nt]);
#pragma unroll
            for (int mt = 0; mt < 4; mt++) {
                int r = wm * 64 + mt * 16 + a_r;
                u32 addr = baseAl + SWZ64((u32)(r * 64 + (ks * 2 + a_h) * 16));
                ldsm_x4(af[mt][0], af[mt][1], af[mt][2], af[mt][3], addr);
            }
#pragma unroll
            for (int mt = 0; mt < 4; mt++)
#pragma unroll
                for (int nt = 0; nt < 4; nt++)
                    mma_bf16(acc[mt][nt], af[mt], bhf[nt]);
        }
        __syncthreads();
    }

    __nv_bfloat16* H = (mat == 0) ? H0 : (mat == 1) ? H1 : H2;
    __nv_bfloat16* L = (mat == 0) ? L0 : (mat == 1) ? L1 : L2;

    int rr = lid >> 2, cc2 = (lid & 3) * 2;
#pragma unroll
    for (int mt = 0; mt < 4; mt++) {
        int r0 = bm + wm * 64 + mt * 16 + rr;
#pragma unroll
        for (int nt = 0; nt < 4; nt++) {
            int col = bn + wn * 32 + nt * 8 + cc2;
            float bb0 = bias[col], bb1 = bias[col + 1];
            float v00 = acc[mt][nt][0] + bb0, v01 = acc[mt][nt][1] + bb1;
            float v10 = acc[mt][nt][2] + bb0, v11 = acc[mt][nt][3] + bb1;
            if (mat == 3) {
                *(float2*)&C[(size_t)r0 * N + col] = make_float2(v00, v01);
                *(float2*)&C[(size_t)(r0 + 8) * N + col] = make_float2(v10, v11);
            } else {
                u32 hi, lo;
                pack_hl(v00, v01, hi, lo);
                *(u32*)&H[(size_t)r0 * N + col] = hi;
                *(u32*)&L[(size_t)r0 * N + col] = lo;
                pack_hl(v10, v11, hi, lo);
                *(u32*)&H[(size_t)(r0 + 8) * N + col] = hi;
                *(u32*)&L[(size_t)(r0 + 8) * N + col] = lo;
            }
        }
    }
}

// ---------------------------------------------------------------------------
// Tensor-core causal flash attention (bf16 hi/lo, fp32 softmax),
// cp.async 2-stage K/V pipeline. Longest CTAs (large qb) launch first.
// RoPE mathematically eliminated (head-only rotation; q.k invariant).
// CTA: 128 q rows, 8 warps (warp = 16 q rows x full 64-col kv tile).
// ---------------------------------------------------------------------------
#define ABQ 128
#define ABK 64
#define OQH 0
#define OQL 16384
#define AKV 32768
#define ASTG 32768
#define ASMEM (AKV + 2 * ASTG)

__global__ __launch_bounds__(256)
void flash_attn_tc(const __nv_bfloat16* __restrict__ qh_,
                   const __nv_bfloat16* __restrict__ ql_,
                   const __nv_bfloat16* __restrict__ kh_,
                   const __nv_bfloat16* __restrict__ kl_,
                   const __nv_bfloat16* __restrict__ vth_,
                   const __nv_bfloat16* __restrict__ vtl_,
                   __nv_bfloat16* __restrict__ aoh,
                   __nv_bfloat16* __restrict__ aol)
{
    extern __shared__ char smc[];
    u32 sb = smem_u32(smc);
    int tid = threadIdx.x, wid = tid / 32, lid = tid % 32;
    int qb = gridDim.x - 1 - blockIdx.x;   // longest work first
    int h = blockIdx.y, b = blockIdx.z;
    int q0 = qb * ABQ;
    int warp_row = q0 + wid * 16;

    // Load Q tile (128x64 hi/lo), SW128 rows
#pragma unroll
    for (int i = 0; i < 4; i++) {
        int c = tid + i * 256;
        int r = c >> 3, ch = c & 7;
        u32 so = SWZ128((u32)(r * 128 + ch * 16));
        size_t g = (size_t)(b * SEQ + q0 + r) * EMB + h * HD + ch * 8;
        *(uint4*)(smc + OQH + so) = *(const uint4*)(qh_ + g);
        *(uint4*)(smc + OQL + so) = *(const uint4*)(ql_ + g);
    }

    int v_r[2], v_ch[2];
#pragma unroll
    for (int i = 0; i < 2; i++) {
        int c = tid + i * 256;
        v_r[i] = c >> 3;
        v_ch[i] = c & 7;
    }

#define ATTN_ISSUE(stage, kb)                                                  \
    do {                                                                       \
        u32 base_ = sb + AKV + (stage) * ASTG;                                 \
        _Pragma("unroll")                                                      \
        for (int i = 0; i < 2; i++) {                                          \
            int r = v_r[i], ch = v_ch[i];                                      \
            u32 so = SWZ128((u32)(r * 128 + ch * 16));                         \
            size_t gk = (size_t)(b * SEQ + (kb) * ABK + r) * EMB + h * HD + ch * 8; \
            size_t gv = ((size_t)((b * NH + h) * HD) + r) * SEQ + (kb) * ABK + ch * 8; \
            cp16(base_ + so, kh_ + gk);                                        \
            cp16(base_ + 8192 + so, kl_ + gk);                                 \
            cp16(base_ + 16384 + so, vth_ + gv);                               \
            cp16(base_ + 24576 + so, vtl_ + gv);                               \
        }                                                                      \
        CP_COMMIT();                                                           \
    } while (0)

    float m_i[2], l_i[2], o[8][4];
    m_i[0] = m_i[1] = -INFINITY;
    l_i[0] = l_i[1] = 0.f;
#pragma unroll
    for (int nt = 0; nt < 8; nt++)
#pragma unroll
        for (int e = 0; e < 4; e++) o[nt][e] = 0.f;

    const float scale = 0.125f;  // 1/sqrt(64)
    int r1 = lid >> 2;
    int a_r = lid & 15, a_h = lid >> 4;
    int b_n = ((lid >> 4) << 3) + (lid & 7), b_h = (lid >> 3) & 1;

    int nkb = 2 * qb + 2;
    ATTN_ISSUE(0, 0);

    for (int kb = 0; kb < nkb; kb++) {
        if (kb + 1 < nkb) {
            ATTN_ISSUE((kb + 1) & 1, kb + 1);
            CP_WAIT(1);
        } else {
            CP_WAIT(0);
        }
        __syncthreads();

        if (kb * ABK <= warp_row + 15) {   // not fully masked
            u32 bk = sb + AKV + (kb & 1) * ASTG;
            u32 okh = bk, okl = bk + 8192, ovh = bk + 16384, ovl = bk + 24576;

            // ---- S = Q K^T (hi/lo, 3 passes) ----
            float s[8][4];
#pragma unroll
            for (int nt = 0; nt < 8; nt++)
#pragma unroll
                for (int e = 0; e < 4; e++) s[nt][e] = 0.f;

#pragma unroll
            for (int kc = 0; kc < 4; kc++) {
                u32 af[4], bhf[8][2], blf[8][2];
                u32 arow = (u32)((wid * 16 + a_r) * 128 + (kc * 2 + a_h) * 16);
                ldsm_x4(af[0], af[1], af[2], af[3], sb + OQH + SWZ128(arow));
#pragma unroll
                for (int g = 0; g < 4; g++) {
                    int n = g * 16 + b_n;
                    u32 off = SWZ128((u32)(n * 128 + (kc * 2 + b_h) * 16));
                    ldsm_x4(bhf[g * 2][0], bhf[g * 2][1],
                            bhf[g * 2 + 1][0], bhf[g * 2 + 1][1], okh + off);
                    ldsm_x4(blf[g * 2][0], blf[g * 2][1],
                            blf[g * 2 + 1][0], blf[g * 2 + 1][1], okl + off);
                }
#pragma unroll
                for (int nt = 0; nt < 8; nt++) mma_bf16(s[nt], af, bhf[nt]);
#pragma unroll
                for (int nt = 0; nt < 8; nt++) mma_bf16(s[nt], af, blf[nt]);
                ldsm_x4(af[0], af[1], af[2], af[3], sb + OQL + SWZ128(arow));
#pragma unroll
                for (int nt = 0; nt < 8; nt++) mma_bf16(s[nt], af, bhf[nt]);
            }

            // ---- scale + causal mask ----
            bool needmask = (kb * ABK + ABK - 1 > warp_row);
#pragma unroll
            for (int nt = 0; nt < 8; nt++) {
#pragma unroll
                for (int e = 0; e < 4; e++) {
                    s[nt][e] *= scale;
                    if (needmask) {
                        int row = warp_row + r1 + ((e >> 1) << 3);
                        int col = kb * ABK + nt * 8 + (lid & 3) * 2 + (e & 1);
                        if (col > row) s[nt][e] = -INFINITY;
                    }
                }
            }

            // ---- online softmax (rows r1, r1+8) ----
#pragma unroll
            for (int half = 0; half < 2; half++) {
                float mx = -INFINITY;
#pragma unroll
                for (int nt = 0; nt < 8; nt++)
                    mx = fmaxf(mx, fmaxf(s[nt][half * 2], s[nt][half * 2 + 1]));
                mx = fmaxf(mx, __shfl_xor_sync(0xffffffffu, mx, 1));
                mx = fmaxf(mx, __shfl_xor_sync(0xffffffffu, mx, 2));
                float m_new = fmaxf(m_i[half], mx);
                float corr = __expf(m_i[half] - m_new);
                m_i[half] = m_new;
                float rs = 0.f;
#pragma unroll
                for (int nt = 0; nt < 8; nt++) {
                    float p0 = __expf(s[nt][half * 2] - m_new);
                    float p1 = __expf(s[nt][half * 2 + 1] - m_new);
                    s[nt][half * 2] = p0;
                    s[nt][half * 2 + 1] = p1;
                    rs += p0 + p1;
                }
                rs += __shfl_xor_sync(0xffffffffu, rs, 1);
                rs += __shfl_xor_sync(0xffffffffu, rs, 2);
                l_i[half] = l_i[half] * corr + rs;
#pragma unroll
                for (int nt = 0; nt < 8; nt++) {
                    o[nt][half * 2] *= corr;
                    o[nt][half * 2 + 1] *= corr;
                }
            }

            // ---- O += P V (hi/lo, 3 passes); P repacked in-register ----
#pragma unroll
            for (int kc = 0; kc < 4; kc++) {
                u32 ph[4], pl[4];
                pack_hl(s[2 * kc][0], s[2 * kc][1], ph[0], pl[0]);
                pack_hl(s[2 * kc][2], s[2 * kc][3], ph[1], pl[1]);
                pack_hl(s[2 * kc + 1][0], s[2 * kc + 1][1], ph[2], pl[2]);
                pack_hl(s[2 * kc + 1][2], s[2 * kc + 1][3], ph[3], pl[3]);

                u32 bvh[8][2], bvl[8][2];
#pragma unroll
                for (int g = 0; g < 4; g++) {
                    int n = g * 16 + b_n;
                    u32 off = SWZ128((u32)(n * 128 + (kc * 2 + b_h) * 16));
                    ldsm_x4(bvh[g * 2][0], bvh[g * 2][1],
                            bvh[g * 2 + 1][0], bvh[g * 2 + 1][1], ovh + off);
                    ldsm_x4(bvl[g * 2][0], bvl[g * 2][1],
                            bvl[g * 2 + 1][0], bvl[g * 2 + 1][1], ovl + off);
                }
#pragma unroll
                for (int nt = 0; nt < 8; nt++) mma_bf16(o[nt], ph, bvh[nt]);
#pragma unroll
                for (int nt = 0; nt < 8; nt++) mma_bf16(o[nt], ph, bvl[nt]);
#pragma unroll
                for (int nt = 0; nt < 8; nt++) mma_bf16(o[nt], pl, bvh[nt]);
            }
        }
        __syncthreads();
    }

    // ---- epilogue: normalize, split to hi/lo bf16, store ----
#pragma unroll
    for (int half = 0; half < 2; half++) {
        float inv = 1.f / l_i[half];
        int row = warp_row + r1 + half * 8;
        size_t base = (size_t)(b * SEQ + row) * EMB + h * HD;
#pragma unroll
        for (int nt = 0; nt < 8; nt++) {
            int col = nt * 8 + (lid & 3) * 2;
            float v0 = o[nt][half * 2] * inv;
            float v1 = o[nt][half * 2 + 1] * inv;
            u32 hi, lo;
            pack_hl(v0, v1, hi, lo);
            *(u32*)&aoh[base + col] = hi;
            *(u32*)&aol[base + col] = lo;
        }
    }
}

// ---------------------------------------------------------------------------
// Launch
// ---------------------------------------------------------------------------
extern "C" void kernel_launch(void* const* d_in, const int* in_sizes, int n_in,
                              void* d_out, int out_size)
{
    const float* x  = (const float*)d_in[0];
    const float* Wq = (const float*)d_in[1];
    const float* bq = (const float*)d_in[2];
    const float* Wk = (const float*)d_in[3];
    const float* bk = (const float*)d_in[4];
    const float* Wv = (const float*)d_in[5];
    const float* bv = (const float*)d_in[6];
    const float* Wo = (const float*)d_in[7];
    const float* bo = (const float*)d_in[8];
    float* out = (float*)d_out;

    __nv_bfloat16 *ah, *al, *bh, *bl, *qh, *ql, *kh, *kl, *vh, *vl, *vth, *vtl;
    cudaGetSymbolAddress((void**)&ah, g_ah);
    cudaGetSymbolAddress((void**)&al, g_al);
    cudaGetSymbolAddress((void**)&bh, g_bh);
    cudaGetSymbolAddress((void**)&bl, g_bl);
    cudaGetSymbolAddress((void**)&qh, g_qh);
    cudaGetSymbolAddress((void**)&ql, g_ql);
    cudaGetSymbolAddress((void**)&kh, g_kh);
    cudaGetSymbolAddress((void**)&kl, g_kl);
    cudaGetSymbolAddress((void**)&vh, g_vh);
    cudaGetSymbolAddress((void**)&vl, g_vl);
    cudaGetSymbolAddress((void**)&vth, g_vth);
    cudaGetSymbolAddress((void**)&vtl, g_vtl);

    cudaFuncSetAttribute(gemm_mma,
                         cudaFuncAttributeMaxDynamicSharedMemorySize, GSMEM);
    cudaFuncSetAttribute(flash_attn_tc,
                         cudaFuncAttributeMaxDynamicSharedMemorySize, ASMEM);

    dim3 ct(32, 8);
    dim3 cg4(EMB / 32, EMB / 32, 4);
    int n4 = MROWS * EMB / 4;
    dim3 qkvgrid(3 * EMB / 128, MROWS / 128);   // (48, 32): fused Q,K,V
    dim3 ogrid(EMB / 128, MROWS / 128);         // (16, 32): out proj
    dim3 vtgrid(SEQ / 32, BSZ * NH * 2);
    dim3 agrid(SEQ / ABQ, NH, BSZ);             // (16, 32, 2)

    // split x; convert all 4 weights
    conv_rows<<<(n4 + 255) / 256, 256>>>(x, ah, al, n4);
    conv_T4<<<cg4, ct>>>(Wq, Wk, Wv, Wo, bh, bl);

    // fused QKV projection -> bf16 hi/lo
    gemm_mma<<<qkvgrid, 256, GSMEM>>>(ah, al, bh, bl, bq, bk, bv, bo,
                                      qh, ql, kh, kl, vh, vl, NULL, 0,
                                      MROWS, EMB);
    conv_vt<<<vtgrid, ct>>>(vh, vl, vth, vtl);

    // attention -> hi/lo into ah/al (x-split no longer needed)
    flash_attn_tc<<<agrid, 256, ASMEM>>>(qh, ql, kh, kl, vth, vtl, ah, al);

    // output projection (mat 3, fp32 out)
    gemm_mma<<<ogrid, 256, GSMEM>>>(ah, al, bh, bl, bq, bk, bv, bo,
                                    qh, ql, kh, kl, vh, vl, out, 3,
                                    MROWS, EMB);
}